// round 5
// baseline (speedup 1.0000x reference)
#include <cuda_runtime.h>

#define NNODES 50000
#define NEDGES 800000
#define FDIM   128
#define HDIM2  256
#define BCAP   64          // bucket capacity per dst node (max degree ~35)

// ---------------- scratch ----------------
__device__ __align__(16) float g_scat0[(size_t)NNODES * FDIM];   // A * E[x]
__device__ __align__(16) float g_h1[(size_t)NNODES * HDIM2];     // relu(. @ W1 + b1)
__device__ __align__(16) float g_t[(size_t)NNODES * FDIM];       // h1 @ W2
__device__ float g_invs[NNODES];
__device__ int   g_cnt[NNODES];
__device__ int   g_xi[NNODES];
__device__ int   g_bucket[(size_t)NNODES * BCAP];
__device__ int   g_not64 = 0;   // 0 -> int64 input, 1 -> int32. Idempotent across replays.

// ---------------- f32x2 helpers ----------------
typedef unsigned long long u64;
__device__ __forceinline__ u64 pk2(float x, float y) {
    u64 r; asm("mov.b64 %0, {%1, %2};" : "=l"(r) : "f"(x), "f"(y)); return r;
}
__device__ __forceinline__ void upk2(u64 v, float& x, float& y) {
    asm("mov.b64 {%0, %1}, %2;" : "=f"(x), "=f"(y) : "l"(v));
}
__device__ __forceinline__ u64 fma2(u64 a, u64 b, u64 c) {
    u64 d; asm("fma.rn.f32x2 %0, %1, %2, %3;" : "=l"(d) : "l"(a), "l"(b), "l"(c)); return d;
}

// ---------------- 1: zero counts + dtype detect ----------------
// int64 little-endian with values < 2^31 -> every odd 32-bit word is 0.
__global__ void zero_detect_kernel(const unsigned int* __restrict__ w) {
    int i = blockIdx.x * blockDim.x + threadIdx.x;
    if (i < NNODES) g_cnt[i] = 0;
    if (i < 2048) { if (w[2 * i + 1]) g_not64 = 1; }
}

// ---------------- 2: convert edges + fill buckets ----------------
__global__ void fill_kernel(const void* __restrict__ ei) {
    int e = blockIdx.x * blockDim.x + threadIdx.x;
    if (e >= NEDGES) return;
    int s, d;
    if (g_not64) {
        const int* p = (const int*)ei;
        s = p[e]; d = p[NEDGES + e];
    } else {
        const long long* p = (const long long*)ei;
        s = (int)p[e]; d = (int)p[NEDGES + e];
    }
    int pos = atomicAdd(&g_cnt[d], 1);
    if (pos < BCAP) g_bucket[(size_t)d * BCAP + pos] = s;
}

// ---------------- 3: convert x ----------------
__global__ void convert_x_kernel(const void* __restrict__ x) {
    int i = blockIdx.x * blockDim.x + threadIdx.x;
    if (i >= NNODES) return;
    g_xi[i] = g_not64 ? ((const int*)x)[i] : (int)((const long long*)x)[i];
}

// ---------------- 4: inverse sqrt degrees ----------------
__global__ void invs_kernel() {
    int i = blockIdx.x * blockDim.x + threadIdx.x;
    if (i >= NNODES) return;
    g_invs[i] = rsqrtf((float)g_cnt[i] + 1.0f);   // +1 = self loop
}

// ---------------- gather: out[n] = invs[n]^2*rows[idx(n)] + sum_e norm*rows[idx(src_e)] (+bias)
// warp per node, lane covers a float4 (128 floats / 32 lanes)
__global__ __launch_bounds__(256)
void gather_kernel(const float* __restrict__ rows, int use_xi,
                   const float* __restrict__ bias, float* __restrict__ outp) {
    int gw = (blockIdx.x * blockDim.x + threadIdx.x) >> 5;
    int lane = threadIdx.x & 31;
    if (gw >= NNODES) return;

    float invn = g_invs[gw];
    int cnt = g_cnt[gw]; if (cnt > BCAP) cnt = BCAP;
    int self = use_xi ? g_xi[gw] : gw;

    float4 v = *reinterpret_cast<const float4*>(rows + (size_t)self * FDIM + lane * 4);
    float nn = invn * invn;
    float4 acc = make_float4(nn * v.x, nn * v.y, nn * v.z, nn * v.w);

    const int* bkt = g_bucket + (size_t)gw * BCAP;
    for (int base = 0; base < cnt; base += 32) {
        int ridx = 0; float ivs = 0.f;
        if (base + lane < cnt) {
            int s = bkt[base + lane];
            ivs = g_invs[s];
            ridx = use_xi ? g_xi[s] : s;
        }
        int m = cnt - base; if (m > 32) m = 32;
#pragma unroll 4
        for (int k = 0; k < m; k++) {
            int rk = __shfl_sync(0xffffffffu, ridx, k);
            float nk = __shfl_sync(0xffffffffu, ivs, k) * invn;
            float4 u = *reinterpret_cast<const float4*>(rows + (size_t)rk * FDIM + lane * 4);
            acc.x += nk * u.x; acc.y += nk * u.y;
            acc.z += nk * u.z; acc.w += nk * u.w;
        }
    }
    if (bias) {
        float4 b = *reinterpret_cast<const float4*>(bias + lane * 4);
        acc.x += b.x; acc.y += b.y; acc.z += b.z; acc.w += b.w;
    }
    *reinterpret_cast<float4*>(outp + (size_t)gw * FDIM + lane * 4) = acc;
}

// ---------------- SGEMM with f32x2 packed FMA ----------------
#define BM 64
#define BN 128
#define BK 32
__global__ __launch_bounds__(256)
void sgemm_kernel(const float* __restrict__ A, const float* __restrict__ B,
                  const float* __restrict__ bias, float* __restrict__ C,
                  int M, int N, int K, int do_relu) {
    __shared__ __align__(16) float As[BM][BK + 1];
    __shared__ __align__(16) float Bs[BK][BN];

    int tid = threadIdx.x;
    int row0 = blockIdx.y * BM;
    int col0 = blockIdx.x * BN;
    int trow = tid >> 4;   // 0..15 -> 4 rows each
    int tcol = tid & 15;   // 0..15 -> 8 cols (4 f32x2 pairs) each

    u64 acc[4][4];
#pragma unroll
    for (int r = 0; r < 4; r++)
#pragma unroll
        for (int c = 0; c < 4; c++) acc[r][c] = 0ull;

    for (int k0 = 0; k0 < K; k0 += BK) {
        for (int i = tid; i < BM * (BK / 4); i += 256) {
            int r = i / (BK / 4);
            int c4 = i % (BK / 4);
            int gr = row0 + r;
            float4 v = make_float4(0.f, 0.f, 0.f, 0.f);
            if (gr < M)
                v = *reinterpret_cast<const float4*>(A + (size_t)gr * K + k0 + c4 * 4);
            As[r][c4 * 4 + 0] = v.x;
            As[r][c4 * 4 + 1] = v.y;
            As[r][c4 * 4 + 2] = v.z;
            As[r][c4 * 4 + 3] = v.w;
        }
        for (int i = tid; i < BK * (BN / 4); i += 256) {
            int r = i / (BN / 4);
            int c4 = i % (BN / 4);
            *reinterpret_cast<float4*>(&Bs[r][c4 * 4]) =
                *reinterpret_cast<const float4*>(B + (size_t)(k0 + r) * N + col0 + c4 * 4);
        }
        __syncthreads();

#pragma unroll
        for (int k = 0; k < BK; k++) {
            const u64* bp = reinterpret_cast<const u64*>(&Bs[k][tcol * 8]);
            u64 b0 = bp[0], b1 = bp[1], b2 = bp[2], b3 = bp[3];
#pragma unroll
            for (int r = 0; r < 4; r++) {
                float a = As[trow * 4 + r][k];
                u64 ap = pk2(a, a);
                acc[r][0] = fma2(ap, b0, acc[r][0]);
                acc[r][1] = fma2(ap, b1, acc[r][1]);
                acc[r][2] = fma2(ap, b2, acc[r][2]);
                acc[r][3] = fma2(ap, b3, acc[r][3]);
            }
        }
        __syncthreads();
    }

    float bv[8];
#pragma unroll
    for (int c = 0; c < 8; c++)
        bv[c] = bias ? bias[col0 + tcol * 8 + c] : 0.f;

#pragma unroll
    for (int r = 0; r < 4; r++) {
        int gr = row0 + trow * 4 + r;
        if (gr >= M) continue;
        float o[8];
#pragma unroll
        for (int c = 0; c < 4; c++) upk2(acc[r][c], o[2 * c], o[2 * c + 1]);
#pragma unroll
        for (int c = 0; c < 8; c++) {
            o[c] += bv[c];
            if (do_relu) o[c] = fmaxf(o[c], 0.f);
        }
        float4 o0 = make_float4(o[0], o[1], o[2], o[3]);
        float4 o1 = make_float4(o[4], o[5], o[6], o[7]);
        *reinterpret_cast<float4*>(C + (size_t)gr * N + col0 + tcol * 8) = o0;
        *reinterpret_cast<float4*>(C + (size_t)gr * N + col0 + tcol * 8 + 4) = o1;
    }
}

// ---------------- launch ----------------
extern "C" void kernel_launch(void* const* d_in, const int* in_sizes, int n_in,
                              void* d_out, int out_size) {
    const void*  x   = d_in[0];                 // (50000,1) int32 or int64
    const void*  ei  = d_in[1];                 // (2,800000) int32 or int64
    const float* emb = (const float*)d_in[2];   // 4096x128
    const float* W1  = (const float*)d_in[3];   // 128x256
    const float* b1  = (const float*)d_in[4];   // 256
    const float* W2  = (const float*)d_in[5];   // 256x128
    const float* b2  = (const float*)d_in[6];   // 128
    float* out = (float*)d_out;                 // 50000x128

    float* scat0p; cudaGetSymbolAddress((void**)&scat0p, g_scat0);
    float* h1p;    cudaGetSymbolAddress((void**)&h1p, g_h1);
    float* tp;     cudaGetSymbolAddress((void**)&tp, g_t);

    // 1) zero counts + dtype detect
    zero_detect_kernel<<<(NNODES + 255) / 256, 256>>>((const unsigned int*)ei);
    // 2) fill buckets (counts via atomic)
    fill_kernel<<<(NEDGES + 255) / 256, 256>>>(ei);
    // 3) convert x indices
    convert_x_kernel<<<(NNODES + 255) / 256, 256>>>(x);
    // 4) invs = rsqrt(deg + 1)
    invs_kernel<<<(NNODES + 255) / 256, 256>>>();
    // 5) gather layer 1: scat0 = A_hat * E[x]
    gather_kernel<<<(NNODES * 32 + 255) / 256, 256>>>(emb, 1, nullptr, scat0p);
    // 6) GEMM1: h1 = relu(scat0 @ W1 + b1)    [captured by ncu slot]
    {
        dim3 grid(HDIM2 / BN, (NNODES + BM - 1) / BM);
        sgemm_kernel<<<grid, 256>>>(scat0p, W1, b1, h1p, NNODES, HDIM2, FDIM, 1);
    }
    // 7) GEMM2: t = h1 @ W2
    {
        dim3 grid(FDIM / BN, (NNODES + BM - 1) / BM);
        sgemm_kernel<<<grid, 256>>>(h1p, W2, nullptr, tp, NNODES, FDIM, HDIM2, 0);
    }
    // 8) gather layer 2: out = A_hat * t + b2
    gather_kernel<<<(NNODES * 32 + 255) / 256, 256>>>(tp, 0, b2, out);
}

// round 6
// speedup vs baseline: 1.1936x; 1.1936x over previous
#include <cuda_runtime.h>

#define NNODES 50000
#define NEDGES 800000
#define FDIM   128
#define HDIM2  256

// ---------------- scratch ----------------
__device__ __align__(16) float g_scat0[(size_t)NNODES * FDIM];   // A * E[x]
__device__ __align__(16) float g_h1[(size_t)NNODES * HDIM2];     // relu(. @ W1 + b1)
__device__ __align__(16) float g_t[(size_t)NNODES * FDIM];       // h1 @ W2
__device__ float g_invs[NNODES];
__device__ int   g_deg[NNODES];
__device__ int   g_src[NEDGES];
__device__ int   g_dst[NEDGES];
__device__ int   g_xi[NNODES];
__device__ int   g_not64 = 0;   // 0 -> int64 input, 1 -> int32 (idempotent)

// ---------------- helpers ----------------
__device__ __forceinline__ void red_add_v4(float* ptr, float4 v) {
    asm volatile("red.global.add.v4.f32 [%0], {%1,%2,%3,%4};"
                 :: "l"(ptr), "f"(v.x), "f"(v.y), "f"(v.z), "f"(v.w)
                 : "memory");
}

// ---------------- 1: zero scat0/out/deg + dtype detect ----------------
// int64 little-endian with values < 2^31 -> every odd 32-bit word is 0.
__global__ void prep1_kernel(float4* __restrict__ out4,
                             const unsigned int* __restrict__ w) {
    int i = blockIdx.x * blockDim.x + threadIdx.x;
    const int n4 = NNODES * FDIM / 4;                        // 1,600,000
    if (i < n4) {
        reinterpret_cast<float4*>(g_scat0)[i] = make_float4(0.f, 0.f, 0.f, 0.f);
        out4[i] = make_float4(0.f, 0.f, 0.f, 0.f);
    }
    if (i < NNODES) g_deg[i] = 0;
    if (i < 2048) { if (w[2 * i + 1]) g_not64 = 1; }
}

// ---------------- 2: convert edges + x, count degrees ----------------
__global__ void prep2_kernel(const void* __restrict__ ei,
                             const void* __restrict__ x) {
    int e = blockIdx.x * blockDim.x + threadIdx.x;
    int is32 = g_not64;
    if (e < NEDGES) {
        int s, d;
        if (is32) {
            const int* p = (const int*)ei;
            s = p[e]; d = p[NEDGES + e];
        } else {
            const long long* p = (const long long*)ei;
            s = (int)p[e]; d = (int)p[NEDGES + e];
        }
        g_src[e] = s;
        g_dst[e] = d;
        atomicAdd(&g_deg[d], 1);
    }
    if (e < NNODES) {
        g_xi[e] = is32 ? ((const int*)x)[e] : (int)((const long long*)x)[e];
    }
}

// ---------------- 3: invs = rsqrt(deg + 1) ----------------
__global__ void invs_kernel() {
    int i = blockIdx.x * blockDim.x + threadIdx.x;
    if (i >= NNODES) return;
    g_invs[i] = rsqrtf((float)g_deg[i] + 1.0f);   // +1 = self loop
}

// ---------------- 4: scatter layer 1: scat0[dst] += norm * emb[x[src]] ------
__global__ void scatter1_kernel(const float* __restrict__ emb) {
    int gw = (blockIdx.x * blockDim.x + threadIdx.x) >> 5;
    int lane = threadIdx.x & 31;
    if (gw >= NEDGES) return;
    int s = g_src[gw];
    int d = g_dst[gw];
    float norm = g_invs[s] * g_invs[d];
    int xs = g_xi[s];
    float4 v = *reinterpret_cast<const float4*>(emb + (size_t)xs * FDIM + lane * 4);
    v.x *= norm; v.y *= norm; v.z *= norm; v.w *= norm;
    red_add_v4(g_scat0 + (size_t)d * FDIM + lane * 4, v);
}

// ---------------- 5: self loop layer 1 ----------------
__global__ void self1_kernel(const float* __restrict__ emb) {
    int gw = (blockIdx.x * blockDim.x + threadIdx.x) >> 5;
    int lane = threadIdx.x & 31;
    if (gw >= NNODES) return;
    float iv = g_invs[gw];
    float nrm = iv * iv;
    int xs = g_xi[gw];
    float4 e = *reinterpret_cast<const float4*>(emb + (size_t)xs * FDIM + lane * 4);
    float4* p = reinterpret_cast<float4*>(g_scat0 + (size_t)gw * FDIM + lane * 4);
    float4 c = *p;
    c.x += nrm * e.x; c.y += nrm * e.y; c.z += nrm * e.z; c.w += nrm * e.w;
    *p = c;
}

// ---------------- SGEMM (scalar FFMA, at roofline) ----------------
#define BM 64
#define BN 128
#define BK 32
__global__ __launch_bounds__(256)
void sgemm_kernel(const float* __restrict__ A, const float* __restrict__ B,
                  const float* __restrict__ bias, float* __restrict__ C,
                  int M, int N, int K, int do_relu) {
    __shared__ float As[BM][BK + 1];
    __shared__ float Bs[BK][BN];

    int tid = threadIdx.x;
    int row0 = blockIdx.y * BM;
    int col0 = blockIdx.x * BN;
    int trow = tid >> 4;   // 0..15 -> 4 rows each
    int tcol = tid & 15;   // 0..15 -> 8 cols each

    float acc[4][8];
#pragma unroll
    for (int r = 0; r < 4; r++)
#pragma unroll
        for (int c = 0; c < 8; c++) acc[r][c] = 0.f;

    for (int k0 = 0; k0 < K; k0 += BK) {
        for (int i = tid; i < BM * (BK / 4); i += 256) {
            int r = i / (BK / 4);
            int c4 = i % (BK / 4);
            int gr = row0 + r;
            float4 v = make_float4(0.f, 0.f, 0.f, 0.f);
            if (gr < M)
                v = *reinterpret_cast<const float4*>(A + (size_t)gr * K + k0 + c4 * 4);
            As[r][c4 * 4 + 0] = v.x;
            As[r][c4 * 4 + 1] = v.y;
            As[r][c4 * 4 + 2] = v.z;
            As[r][c4 * 4 + 3] = v.w;
        }
        for (int i = tid; i < BK * (BN / 4); i += 256) {
            int r = i / (BN / 4);
            int c4 = i % (BN / 4);
            *reinterpret_cast<float4*>(&Bs[r][c4 * 4]) =
                *reinterpret_cast<const float4*>(B + (size_t)(k0 + r) * N + col0 + c4 * 4);
        }
        __syncthreads();

#pragma unroll
        for (int k = 0; k < BK; k++) {
            float a[4];
#pragma unroll
            for (int r = 0; r < 4; r++) a[r] = As[trow * 4 + r][k];
            float4 b0 = *reinterpret_cast<float4*>(&Bs[k][tcol * 8]);
            float4 b1 = *reinterpret_cast<float4*>(&Bs[k][tcol * 8 + 4]);
#pragma unroll
            for (int r = 0; r < 4; r++) {
                acc[r][0] += a[r] * b0.x;
                acc[r][1] += a[r] * b0.y;
                acc[r][2] += a[r] * b0.z;
                acc[r][3] += a[r] * b0.w;
                acc[r][4] += a[r] * b1.x;
                acc[r][5] += a[r] * b1.y;
                acc[r][6] += a[r] * b1.z;
                acc[r][7] += a[r] * b1.w;
            }
        }
        __syncthreads();
    }

    float bv[8];
#pragma unroll
    for (int c = 0; c < 8; c++)
        bv[c] = bias ? bias[col0 + tcol * 8 + c] : 0.f;

#pragma unroll
    for (int r = 0; r < 4; r++) {
        int gr = row0 + trow * 4 + r;
        if (gr >= M) continue;
        float4 o0, o1;
        o0.x = acc[r][0] + bv[0]; o0.y = acc[r][1] + bv[1];
        o0.z = acc[r][2] + bv[2]; o0.w = acc[r][3] + bv[3];
        o1.x = acc[r][4] + bv[4]; o1.y = acc[r][5] + bv[5];
        o1.z = acc[r][6] + bv[6]; o1.w = acc[r][7] + bv[7];
        if (do_relu) {
            o0.x = fmaxf(o0.x, 0.f); o0.y = fmaxf(o0.y, 0.f);
            o0.z = fmaxf(o0.z, 0.f); o0.w = fmaxf(o0.w, 0.f);
            o1.x = fmaxf(o1.x, 0.f); o1.y = fmaxf(o1.y, 0.f);
            o1.z = fmaxf(o1.z, 0.f); o1.w = fmaxf(o1.w, 0.f);
        }
        *reinterpret_cast<float4*>(C + (size_t)gr * N + col0 + tcol * 8) = o0;
        *reinterpret_cast<float4*>(C + (size_t)gr * N + col0 + tcol * 8 + 4) = o1;
    }
}

// ---------------- scatter layer 2: out[dst] += norm * t[src] ----------------
__global__ void scatter2_kernel(float* __restrict__ out) {
    int gw = (blockIdx.x * blockDim.x + threadIdx.x) >> 5;
    int lane = threadIdx.x & 31;
    if (gw >= NEDGES) return;
    int s = g_src[gw];
    int d = g_dst[gw];
    float norm = g_invs[s] * g_invs[d];
    float4 v = *reinterpret_cast<const float4*>(g_t + (size_t)s * FDIM + lane * 4);
    v.x *= norm; v.y *= norm; v.z *= norm; v.w *= norm;
    red_add_v4(out + (size_t)d * FDIM + lane * 4, v);
}

// ---------------- final: out += invs^2 * t + b2 ------------------------------
__global__ void final_kernel(const float* __restrict__ b2,
                             float* __restrict__ out) {
    int gw = (blockIdx.x * blockDim.x + threadIdx.x) >> 5;
    int lane = threadIdx.x & 31;
    if (gw >= NNODES) return;
    float iv = g_invs[gw];
    float nrm = iv * iv;
    float4 t = *reinterpret_cast<const float4*>(g_t + (size_t)gw * FDIM + lane * 4);
    float4 b = *reinterpret_cast<const float4*>(b2 + lane * 4);
    float4* p = reinterpret_cast<float4*>(out + (size_t)gw * FDIM + lane * 4);
    float4 c = *p;
    c.x += nrm * t.x + b.x;
    c.y += nrm * t.y + b.y;
    c.z += nrm * t.z + b.z;
    c.w += nrm * t.w + b.w;
    *p = c;
}

// ---------------- launch ----------------
extern "C" void kernel_launch(void* const* d_in, const int* in_sizes, int n_in,
                              void* d_out, int out_size) {
    const void*  x   = d_in[0];                 // (50000,1) int32 or int64
    const void*  ei  = d_in[1];                 // (2,800000) int32 or int64
    const float* emb = (const float*)d_in[2];   // 4096x128
    const float* W1  = (const float*)d_in[3];   // 128x256
    const float* b1  = (const float*)d_in[4];   // 256
    const float* W2  = (const float*)d_in[5];   // 256x128
    const float* b2  = (const float*)d_in[6];   // 128
    float* out = (float*)d_out;                 // 50000x128

    float* scat0p; cudaGetSymbolAddress((void**)&scat0p, g_scat0);
    float* h1p;    cudaGetSymbolAddress((void**)&h1p, g_h1);
    float* tp;     cudaGetSymbolAddress((void**)&tp, g_t);

    // 1) zero + detect
    {
        int n4 = NNODES * FDIM / 4;
        prep1_kernel<<<(n4 + 255) / 256, 256>>>((float4*)out, (const unsigned int*)ei);
    }
    // 2) convert edges + x, degree count
    prep2_kernel<<<(NEDGES + 255) / 256, 256>>>(ei, x);
    // 3) invs
    invs_kernel<<<(NNODES + 255) / 256, 256>>>();
    // 4) scatter1  <-- ncu capture slot
    scatter1_kernel<<<(NEDGES * 32) / 256, 256>>>(emb);
    // 5) self loop layer 1
    self1_kernel<<<(NNODES * 32 + 255) / 256, 256>>>(emb);
    // 6) GEMM1: h1 = relu(scat0 @ W1 + b1)
    {
        dim3 grid(HDIM2 / BN, (NNODES + BM - 1) / BM);
        sgemm_kernel<<<grid, 256>>>(scat0p, W1, b1, h1p, NNODES, HDIM2, FDIM, 1);
    }
    // 7) GEMM2: t = h1 @ W2
    {
        dim3 grid(FDIM / BN, (NNODES + BM - 1) / BM);
        sgemm_kernel<<<grid, 256>>>(h1p, W2, nullptr, tp, NNODES, FDIM, HDIM2, 0);
    }
    // 8) scatter2
    scatter2_kernel<<<(NEDGES * 32) / 256, 256>>>(out);
    // 9) self loop + bias
    final_kernel<<<(NNODES * 32 + 255) / 256, 256>>>(b2, out);
}

// round 9
// speedup vs baseline: 1.7542x; 1.4697x over previous
#include <cuda_runtime.h>
#include <cuda_bf16.h>
#include <cstdint>

#define NNODES 50000
#define NEDGES 800000
#define FDIM   128
#define HDIM2  256

// ---------------- scratch ----------------
__device__ __align__(16) float g_scat0[(size_t)NNODES * FDIM];   // A_hat * E[x] (fp32)
__device__ __align__(16) __nv_bfloat16 g_ahi[(size_t)NNODES * FDIM];
__device__ __align__(16) __nv_bfloat16 g_alo[(size_t)NNODES * FDIM];
__device__ __align__(16) __nv_bfloat16 g_h1hi[(size_t)NNODES * HDIM2];
__device__ __align__(16) __nv_bfloat16 g_h1lo[(size_t)NNODES * HDIM2];
__device__ __align__(16) float g_t[(size_t)NNODES * FDIM];       // h1 @ W2 (fp32)
__device__ float g_invs[NNODES];
__device__ int   g_deg[NNODES];
__device__ int   g_src[NEDGES];
__device__ int   g_dst[NEDGES];
__device__ int   g_xi[NNODES];
__device__ int   g_not64 = 0;   // 0 -> int64 input, 1 -> int32 (idempotent)
// split transposed weights: W1T [256][128], W2T [128][256]
__device__ __align__(16) __nv_bfloat16 g_w1t_hi[HDIM2 * FDIM];
__device__ __align__(16) __nv_bfloat16 g_w1t_lo[HDIM2 * FDIM];
__device__ __align__(16) __nv_bfloat16 g_w2t_hi[FDIM * HDIM2];
__device__ __align__(16) __nv_bfloat16 g_w2t_lo[FDIM * HDIM2];

// ---------------- helpers ----------------
__device__ __forceinline__ void red_add_v4(float* ptr, float4 v) {
    asm volatile("red.global.add.v4.f32 [%0], {%1,%2,%3,%4};"
                 :: "l"(ptr), "f"(v.x), "f"(v.y), "f"(v.z), "f"(v.w)
                 : "memory");
}
__device__ __forceinline__ uint32_t smem_u32(const void* p) {
    uint32_t a;
    asm("{ .reg .u64 t; cvta.to.shared.u64 t, %1; cvt.u32.u64 %0, t; }"
        : "=r"(a) : "l"(p));
    return a;
}
// split a pair of fp32 into bf16 hi + bf16 lo packed words
__device__ __forceinline__ void split2(float a, float b, uint32_t& h, uint32_t& l) {
    __nv_bfloat162 hb = __float22bfloat162_rn(make_float2(a, b));
    float2 hf = __bfloat1622float2(hb);
    __nv_bfloat162 lb = __float22bfloat162_rn(make_float2(a - hf.x, b - hf.y));
    h = *reinterpret_cast<uint32_t*>(&hb);
    l = *reinterpret_cast<uint32_t*>(&lb);
}

#define LDSM4(r, a) asm volatile( \
    "ldmatrix.sync.aligned.m8n8.x4.shared.b16 {%0,%1,%2,%3}, [%4];" \
    : "=r"((r)[0]), "=r"((r)[1]), "=r"((r)[2]), "=r"((r)[3]) : "r"(a))
#define LDSM2(r, a) asm volatile( \
    "ldmatrix.sync.aligned.m8n8.x2.shared.b16 {%0,%1}, [%2];" \
    : "=r"((r)[0]), "=r"((r)[1]) : "r"(a))
#define MMA_BF16(c, a, b) asm volatile( \
    "mma.sync.aligned.m16n8k16.row.col.f32.bf16.bf16.f32 " \
    "{%0,%1,%2,%3}, {%4,%5,%6,%7}, {%8,%9}, {%0,%1,%2,%3};" \
    : "+f"((c)[0]), "+f"((c)[1]), "+f"((c)[2]), "+f"((c)[3]) \
    : "r"((a)[0]), "r"((a)[1]), "r"((a)[2]), "r"((a)[3]), \
      "r"((b)[0]), "r"((b)[1]))

// ---------------- 1: zero deg + dtype detect ----------------
__global__ void prep1_kernel(const unsigned int* __restrict__ w) {
    int i = blockIdx.x * blockDim.x + threadIdx.x;
    if (i < NNODES) g_deg[i] = 0;
    if (i < 2048) { if (w[2 * i + 1]) g_not64 = 1; }
}

// ---------------- 2: convert edges + x, count degrees ----------------
__global__ void prep2_kernel(const void* __restrict__ ei,
                             const void* __restrict__ x) {
    int e = blockIdx.x * blockDim.x + threadIdx.x;
    int is32 = g_not64;
    if (e < NEDGES) {
        int s, d;
        if (is32) {
            const int* p = (const int*)ei;
            s = p[e]; d = p[NEDGES + e];
        } else {
            const long long* p = (const long long*)ei;
            s = (int)p[e]; d = (int)p[NEDGES + e];
        }
        g_src[e] = s;
        g_dst[e] = d;
        atomicAdd(&g_deg[d], 1);
    }
    if (e < NNODES) {
        g_xi[e] = is32 ? ((const int*)x)[e] : (int)((const long long*)x)[e];
    }
}

// ---------------- 3: invs + init scat0 with self-loop term ----------------
__global__ void invs_init1_kernel(const float* __restrict__ emb) {
    int gw = (blockIdx.x * blockDim.x + threadIdx.x) >> 5;
    int lane = threadIdx.x & 31;
    if (gw >= NNODES) return;
    float iv = rsqrtf((float)g_deg[gw] + 1.0f);
    if (lane == 0) g_invs[gw] = iv;
    float nn = iv * iv;
    int xs = g_xi[gw];
    float4 e = *reinterpret_cast<const float4*>(emb + (size_t)xs * FDIM + lane * 4);
    e.x *= nn; e.y *= nn; e.z *= nn; e.w *= nn;
    *reinterpret_cast<float4*>(g_scat0 + (size_t)gw * FDIM + lane * 4) = e;
}

// ---------------- 4: scatter layer 1 (ncu slot) ----------------
__global__ void scatter1_kernel(const float* __restrict__ emb) {
    int gw = (blockIdx.x * blockDim.x + threadIdx.x) >> 5;
    int lane = threadIdx.x & 31;
    if (gw >= NEDGES) return;
    int s = g_src[gw];
    int d = g_dst[gw];
    float norm = g_invs[s] * g_invs[d];
    int xs = g_xi[s];
    float4 v = *reinterpret_cast<const float4*>(emb + (size_t)xs * FDIM + lane * 4);
    v.x *= norm; v.y *= norm; v.z *= norm; v.w *= norm;
    red_add_v4(g_scat0 + (size_t)d * FDIM + lane * 4, v);
}

// ---------------- 5: split scat0 fp32 -> bf16 hi/lo ----------------
__global__ void splitA_kernel() {
    int i = blockIdx.x * blockDim.x + threadIdx.x;   // one per 8 floats
    if (i >= NNODES * FDIM / 8) return;
    const float4* p = reinterpret_cast<const float4*>(g_scat0) + (size_t)i * 2;
    float4 v0 = p[0], v1 = p[1];
    float f[8] = {v0.x, v0.y, v0.z, v0.w, v1.x, v1.y, v1.z, v1.w};
    uint32_t hi[4], lo[4];
#pragma unroll
    for (int q = 0; q < 4; q++) split2(f[2 * q], f[2 * q + 1], hi[q], lo[q]);
    reinterpret_cast<uint4*>(g_ahi)[i] = make_uint4(hi[0], hi[1], hi[2], hi[3]);
    reinterpret_cast<uint4*>(g_alo)[i] = make_uint4(lo[0], lo[1], lo[2], lo[3]);
}

// ---------------- 6: weight transpose + hi/lo split ----------------
__global__ void wsplit_kernel(const float* __restrict__ W1,
                              const float* __restrict__ W2) {
    int t = blockIdx.x * blockDim.x + threadIdx.x;
    if (t < FDIM * HDIM2) {               // W1: [128][256] -> W1T [256][128]
        int n = t / FDIM, k = t % FDIM;
        float w = W1[(size_t)k * HDIM2 + n];
        __nv_bfloat16 hi = __float2bfloat16(w);
        __nv_bfloat16 lo = __float2bfloat16(w - __bfloat162float(hi));
        g_w1t_hi[(size_t)n * FDIM + k] = hi;
        g_w1t_lo[(size_t)n * FDIM + k] = lo;
    } else if (t < 2 * FDIM * HDIM2) {    // W2: [256][128] -> W2T [128][256]
        int u = t - FDIM * HDIM2;
        int n = u / HDIM2, k = u % HDIM2;
        float w = W2[(size_t)k * FDIM + n];
        __nv_bfloat16 hi = __float2bfloat16(w);
        __nv_bfloat16 lo = __float2bfloat16(w - __bfloat162float(hi));
        g_w2t_hi[(size_t)n * HDIM2 + k] = hi;
        g_w2t_lo[(size_t)n * HDIM2 + k] = lo;
    }
}

// ---------------- split-bf16 HMMA GEMM ----------------
// C[M,Ntot] = (Ahi+Alo)[M,K] @ (BThi+BTlo)[Ntot,K]^T  (+bias)(relu)
// BM=128, BN=64, BK=32; 8 warps 4(m) x 2(n); warp tile 32x32 = 2x4 m16n8k16.
// 3 MMAs per frag: Ahi*Bhi + Ahi*Blo + Alo*Bhi (fp32 accum).
#define STR 56   // smem row stride in bf16: 112B, 16B-aligned, conflict-free ldmatrix
__global__ __launch_bounds__(256)
void gemm_mma_kernel(const __nv_bfloat16* __restrict__ Ahi,
                     const __nv_bfloat16* __restrict__ Alo,
                     const __nv_bfloat16* __restrict__ Bhi,
                     const __nv_bfloat16* __restrict__ Blo,
                     const float* __restrict__ bias,
                     float* __restrict__ outf,
                     __nv_bfloat16* __restrict__ outhi,
                     __nv_bfloat16* __restrict__ outlo,
                     int M, int Ntot, int K, int do_relu) {
    __shared__ __align__(16) __nv_bfloat16 sm[21504];   // 43008 B
    const int B_AHI = 0;               // bytes
    const int B_ALO = 14336;           // 128*56*2
    const int B_BHI = 28672;
    const int B_BLO = 35840;           // +64*56*2

    int tid = threadIdx.x;
    int lane = tid & 31;
    int wid = tid >> 5;
    int wm = wid & 3, wn = wid >> 2;
    int row0 = blockIdx.y * 128;
    int n0 = blockIdx.x * 64;
    uint32_t smb = smem_u32(sm);
    char* smc = reinterpret_cast<char*>(sm);

    float acc[2][4][4];
#pragma unroll
    for (int mt = 0; mt < 2; mt++)
#pragma unroll
        for (int nt = 0; nt < 4; nt++)
#pragma unroll
            for (int q = 0; q < 4; q++) acc[mt][nt][q] = 0.f;

    int arow = tid >> 1, ahalf = tid & 1;     // A: 2 threads/row, 16 bf16 each
    int brow = tid >> 2, bseg = tid & 3;      // B: 4 threads/row, 8 bf16 each
    int nch = K >> 5;

    for (int c = 0; c < nch; c++) {
        // ---- stage A [128 x 32] bf16 hi/lo ----
        {
            bool v = (row0 + arow) < M;
            size_t off = (size_t)(row0 + arow) * K + c * 32 + ahalf * 16;
            uint4 z = make_uint4(0, 0, 0, 0);
            uint4 h0 = z, h1 = z, l0 = z, l1 = z;
            if (v) {
                h0 = *reinterpret_cast<const uint4*>(Ahi + off);
                h1 = *reinterpret_cast<const uint4*>(Ahi + off + 8);
                l0 = *reinterpret_cast<const uint4*>(Alo + off);
                l1 = *reinterpret_cast<const uint4*>(Alo + off + 8);
            }
            int bo = (arow * STR + ahalf * 16) * 2;
            *reinterpret_cast<uint4*>(smc + B_AHI + bo) = h0;
            *reinterpret_cast<uint4*>(smc + B_AHI + bo + 16) = h1;
            *reinterpret_cast<uint4*>(smc + B_ALO + bo) = l0;
            *reinterpret_cast<uint4*>(smc + B_ALO + bo + 16) = l1;
        }
        // ---- stage B [64 x 32] bf16 hi/lo ----
        {
            size_t off = (size_t)(n0 + brow) * K + c * 32 + bseg * 8;
            uint4 h = *reinterpret_cast<const uint4*>(Bhi + off);
            uint4 l = *reinterpret_cast<const uint4*>(Blo + off);
            int bo = (brow * STR + bseg * 8) * 2;
            *reinterpret_cast<uint4*>(smc + B_BHI + bo) = h;
            *reinterpret_cast<uint4*>(smc + B_BLO + bo) = l;
        }
        __syncthreads();

#pragma unroll
        for (int ks = 0; ks < 2; ks++) {
            uint32_t ah[2][4], al[2][4], bh[4][2], bl[4][2];
#pragma unroll
            for (int mt = 0; mt < 2; mt++) {
                uint32_t ad = smb +
                    ((wm * 32 + mt * 16 + (lane & 15)) * STR +
                     ks * 16 + ((lane >> 4) << 3)) * 2;
                LDSM4(ah[mt], ad + B_AHI);
                LDSM4(al[mt], ad + B_ALO);
            }
#pragma unroll
            for (int nt = 0; nt < 4; nt++) {
                uint32_t bd = smb +
                    ((wn * 32 + nt * 8 + (lane & 7)) * STR +
                     ks * 16 + ((lane >> 3) & 1) * 8) * 2;
                LDSM2(bh[nt], bd + B_BHI);
                LDSM2(bl[nt], bd + B_BLO);
            }
#pragma unroll
            for (int mt = 0; mt < 2; mt++)
#pragma unroll
                for (int nt = 0; nt < 4; nt++) {
                    MMA_BF16(acc[mt][nt], ah[mt], bh[nt]);
                    MMA_BF16(acc[mt][nt], ah[mt], bl[nt]);
                    MMA_BF16(acc[mt][nt], al[mt], bh[nt]);
                }
        }
        __syncthreads();
    }

    // ---- epilogue ----
    int g = lane >> 2, t4 = lane & 3;
#pragma unroll
    for (int mt = 0; mt < 2; mt++) {
        int r0g = row0 + wm * 32 + mt * 16 + g;
#pragma unroll
        for (int nt = 0; nt < 4; nt++) {
            int col = n0 + wn * 32 + nt * 8 + 2 * t4;
            float* a = acc[mt][nt];
            if (bias) {
                float2 bv = *reinterpret_cast<const float2*>(bias + col);
                a[0] += bv.x; a[1] += bv.y; a[2] += bv.x; a[3] += bv.y;
            }
            if (do_relu) {
                a[0] = fmaxf(a[0], 0.f); a[1] = fmaxf(a[1], 0.f);
                a[2] = fmaxf(a[2], 0.f); a[3] = fmaxf(a[3], 0.f);
            }
            if (outf) {
                if (r0g < M)
                    *reinterpret_cast<float2*>(outf + (size_t)r0g * Ntot + col) =
                        make_float2(a[0], a[1]);
                if (r0g + 8 < M)
                    *reinterpret_cast<float2*>(outf + (size_t)(r0g + 8) * Ntot + col) =
                        make_float2(a[2], a[3]);
            }
            if (outhi) {
                uint32_t h, l;
                if (r0g < M) {
                    split2(a[0], a[1], h, l);
                    size_t wi = ((size_t)r0g * Ntot + col) >> 1;
                    reinterpret_cast<uint32_t*>(outhi)[wi] = h;
                    reinterpret_cast<uint32_t*>(outlo)[wi] = l;
                }
                if (r0g + 8 < M) {
                    split2(a[2], a[3], h, l);
                    size_t wi = ((size_t)(r0g + 8) * Ntot + col) >> 1;
                    reinterpret_cast<uint32_t*>(outhi)[wi] = h;
                    reinterpret_cast<uint32_t*>(outlo)[wi] = l;
                }
            }
        }
    }
}

// ---------------- init out with self-loop + bias ----------------
__global__ void init2_kernel(const float* __restrict__ b2,
                             float* __restrict__ out) {
    int gw = (blockIdx.x * blockDim.x + threadIdx.x) >> 5;
    int lane = threadIdx.x & 31;
    if (gw >= NNODES) return;
    float iv = g_invs[gw];
    float nn = iv * iv;
    float4 t = *reinterpret_cast<const float4*>(g_t + (size_t)gw * FDIM + lane * 4);
    float4 b = *reinterpret_cast<const float4*>(b2 + lane * 4);
    float4 o;
    o.x = nn * t.x + b.x; o.y = nn * t.y + b.y;
    o.z = nn * t.z + b.z; o.w = nn * t.w + b.w;
    *reinterpret_cast<float4*>(out + (size_t)gw * FDIM + lane * 4) = o;
}

// ---------------- scatter layer 2 ----------------
__global__ void scatter2_kernel(float* __restrict__ out) {
    int gw = (blockIdx.x * blockDim.x + threadIdx.x) >> 5;
    int lane = threadIdx.x & 31;
    if (gw >= NEDGES) return;
    int s = g_src[gw];
    int d = g_dst[gw];
    float norm = g_invs[s] * g_invs[d];
    float4 v = *reinterpret_cast<const float4*>(g_t + (size_t)s * FDIM + lane * 4);
    v.x *= norm; v.y *= norm; v.z *= norm; v.w *= norm;
    red_add_v4(out + (size_t)d * FDIM + lane * 4, v);
}

// ---------------- launch ----------------
extern "C" void kernel_launch(void* const* d_in, const int* in_sizes, int n_in,
                              void* d_out, int out_size) {
    const void*  x   = d_in[0];
    const void*  ei  = d_in[1];
    const float* emb = (const float*)d_in[2];   // 4096x128
    const float* W1  = (const float*)d_in[3];   // 128x256
    const float* b1  = (const float*)d_in[4];   // 256
    const float* W2  = (const float*)d_in[5];   // 256x128
    const float* b2  = (const float*)d_in[6];   // 128
    float* out = (float*)d_out;                 // 50000x128

    float* tp;  cudaGetSymbolAddress((void**)&tp, g_t);
    __nv_bfloat16 *ahi, *alo, *h1hi, *h1lo, *w1h, *w1l, *w2h, *w2l;
    cudaGetSymbolAddress((void**)&ahi,  g_ahi);
    cudaGetSymbolAddress((void**)&alo,  g_alo);
    cudaGetSymbolAddress((void**)&h1hi, g_h1hi);
    cudaGetSymbolAddress((void**)&h1lo, g_h1lo);
    cudaGetSymbolAddress((void**)&w1h,  g_w1t_hi);
    cudaGetSymbolAddress((void**)&w1l,  g_w1t_lo);
    cudaGetSymbolAddress((void**)&w2h,  g_w2t_hi);
    cudaGetSymbolAddress((void**)&w2l,  g_w2t_lo);

    // 1) zero deg + dtype detect
    prep1_kernel<<<(NNODES + 255) / 256, 256>>>((const unsigned int*)ei);
    // 2) convert edges + x, degree count
    prep2_kernel<<<(NEDGES + 255) / 256, 256>>>(ei, x);
    // 3) invs + scat0 self-loop init
    invs_init1_kernel<<<(NNODES * 32 + 255) / 256, 256>>>(emb);
    // 4) scatter1   <-- ncu capture slot
    scatter1_kernel<<<(NEDGES * 32) / 256, 256>>>(emb);
    // 5) split scat0 -> bf16 hi/lo
    splitA_kernel<<<(NNODES * FDIM / 8 + 255) / 256, 256>>>();
    // 6) weight transpose + split
    wsplit_kernel<<<(2 * FDIM * HDIM2 + 255) / 256, 256>>>(W1, W2);
    // 7) GEMM1: h1(hi/lo) = relu(scat0 @ W1 + b1)   [M=50000, N=256, K=128]
    {
        dim3 grid(HDIM2 / 64, (NNODES + 127) / 128);
        gemm_mma_kernel<<<grid, 256>>>(ahi, alo, w1h, w1l, b1,
                                       nullptr, h1hi, h1lo,
                                       NNODES, HDIM2, FDIM, 1);
    }
    // 8) GEMM2: t = h1 @ W2                          [M=50000, N=128, K=256]
    {
        dim3 grid(FDIM / 64, (NNODES + 127) / 128);
        gemm_mma_kernel<<<grid, 256>>>(h1hi, h1lo, w2h, w2l, nullptr,
                                       tp, nullptr, nullptr,
                                       NNODES, FDIM, HDIM2, 0);
    }
    // 9) out = invs^2 * t + b2
    init2_kernel<<<(NNODES * 32 + 255) / 256, 256>>>(b2, out);
    // 10) scatter2
    scatter2_kernel<<<(NEDGES * 32) / 256, 256>>>(out);
}

// round 11
// speedup vs baseline: 1.7795x; 1.0144x over previous
#include <cuda_runtime.h>
#include <cuda_bf16.h>
#include <cstdint>

#define NNODES 50000
#define NEDGES 800000
#define FDIM   128
#define HDIM2  256

// ---------------- scratch ----------------
__device__ __align__(16) __nv_bfloat16 g_ahi[(size_t)NNODES * FDIM];
__device__ __align__(16) __nv_bfloat16 g_alo[(size_t)NNODES * FDIM];
__device__ __align__(16) __nv_bfloat16 g_h1hi[(size_t)NNODES * HDIM2];
__device__ __align__(16) __nv_bfloat16 g_h1lo[(size_t)NNODES * HDIM2];
__device__ __align__(16) float g_t[(size_t)NNODES * FDIM];       // h1 @ W2 (fp32)
__device__ float g_invs[NNODES];
__device__ int   g_deg[NNODES];
__device__ int   g_ptr[NNODES];
__device__ int   g_cur[NNODES];
__device__ int   g_src[NEDGES];
__device__ int   g_dst[NEDGES];
__device__ __align__(8) int2 g_adj[NEDGES];   // (src, norm-bits) sorted by dst
__device__ int   g_xi[NNODES];
__device__ int   g_not64 = 0;   // 0 -> int64 input, 1 -> int32 (idempotent)
// split transposed weights: W1T [256][128], W2T [128][256]
__device__ __align__(16) __nv_bfloat16 g_w1t_hi[HDIM2 * FDIM];
__device__ __align__(16) __nv_bfloat16 g_w1t_lo[HDIM2 * FDIM];
__device__ __align__(16) __nv_bfloat16 g_w2t_hi[FDIM * HDIM2];
__device__ __align__(16) __nv_bfloat16 g_w2t_lo[FDIM * HDIM2];

// ---------------- helpers ----------------
__device__ __forceinline__ uint32_t smem_u32(const void* p) {
    uint32_t a;
    asm("{ .reg .u64 t; cvta.to.shared.u64 t, %1; cvt.u32.u64 %0, t; }"
        : "=r"(a) : "l"(p));
    return a;
}
__device__ __forceinline__ void split2(float a, float b, uint32_t& h, uint32_t& l) {
    __nv_bfloat162 hb = __float22bfloat162_rn(make_float2(a, b));
    float2 hf = __bfloat1622float2(hb);
    __nv_bfloat162 lb = __float22bfloat162_rn(make_float2(a - hf.x, b - hf.y));
    h = *reinterpret_cast<uint32_t*>(&hb);
    l = *reinterpret_cast<uint32_t*>(&lb);
}

#define LDSM4(r, a) asm volatile( \
    "ldmatrix.sync.aligned.m8n8.x4.shared.b16 {%0,%1,%2,%3}, [%4];" \
    : "=r"((r)[0]), "=r"((r)[1]), "=r"((r)[2]), "=r"((r)[3]) : "r"(a))
#define LDSM2(r, a) asm volatile( \
    "ldmatrix.sync.aligned.m8n8.x2.shared.b16 {%0,%1}, [%2];" \
    : "=r"((r)[0]), "=r"((r)[1]) : "r"(a))
#define MMA_BF16(c, a, b) asm volatile( \
    "mma.sync.aligned.m16n8k16.row.col.f32.bf16.bf16.f32 " \
    "{%0,%1,%2,%3}, {%4,%5,%6,%7}, {%8,%9}, {%0,%1,%2,%3};" \
    : "+f"((c)[0]), "+f"((c)[1]), "+f"((c)[2]), "+f"((c)[3]) \
    : "r"((a)[0]), "r"((a)[1]), "r"((a)[2]), "r"((a)[3]), \
      "r"((b)[0]), "r"((b)[1]))

// ---------------- 1: zero deg + dtype detect ----------------
__global__ void prep1_kernel(const unsigned int* __restrict__ w) {
    int i = blockIdx.x * blockDim.x + threadIdx.x;
    if (i < NNODES) g_deg[i] = 0;
    if (i < 2048) { if (w[2 * i + 1]) g_not64 = 1; }
}

// ---------------- 2: convert edges + x, count degrees ----------------
__global__ void prep2_kernel(const void* __restrict__ ei,
                             const void* __restrict__ x) {
    int e = blockIdx.x * blockDim.x + threadIdx.x;
    int is32 = g_not64;
    if (e < NEDGES) {
        int s, d;
        if (is32) {
            const int* p = (const int*)ei;
            s = p[e]; d = p[NEDGES + e];
        } else {
            const long long* p = (const long long*)ei;
            s = (int)p[e]; d = (int)p[NEDGES + e];
        }
        g_src[e] = s;
        g_dst[e] = d;
        atomicAdd(&g_deg[d], 1);
    }
    if (e < NNODES) {
        g_xi[e] = is32 ? ((const int*)x)[e] : (int)((const long long*)x)[e];
    }
}

// ---------------- 3: exclusive scan of deg -> ptr/cur, and invs ----------------
// single block, 1024 threads, 49 bins each (49*1024 >= 50000)
__global__ __launch_bounds__(1024)
void scaninvs_kernel() {
    __shared__ int part[1024];
    int t = threadIdx.x;
    int lo = t * 49;
    int hi = lo + 49; if (hi > NNODES) hi = NNODES;
    int sum = 0;
    for (int i = lo; i < hi; i++) sum += g_deg[i];
    part[t] = sum;
    __syncthreads();
    for (int off = 1; off < 1024; off <<= 1) {
        int v = (t >= off) ? part[t - off] : 0;
        __syncthreads();
        part[t] += v;
        __syncthreads();
    }
    int base = (t > 0) ? part[t - 1] : 0;
    for (int i = lo; i < hi; i++) {
        g_ptr[i] = base;
        g_cur[i] = base;
        g_invs[i] = rsqrtf((float)g_deg[i] + 1.0f);
        base += g_deg[i];
    }
}

// ---------------- 4: fill CSR adjacency (src, norm) ----------------
__global__ void fill_kernel() {
    int e = blockIdx.x * blockDim.x + threadIdx.x;
    if (e >= NEDGES) return;
    int s = g_src[e];
    int d = g_dst[e];
    float norm = g_invs[s] * g_invs[d];
    int pos = atomicAdd(&g_cur[d], 1);
    g_adj[pos] = make_int2(s, __float_as_int(norm));
}

// ---------------- gather: warp per node ----------------
// acc = invs^2 * rows[self] + sum_k norm_k * rows[idx_k]  (+bias)
// mode A (outhi!=0): idx via xi[], write bf16 hi/lo split
// mode B: idx direct, write fp32 (+bias)
__global__ __launch_bounds__(256)
void gather_kernel(const float* __restrict__ rows, int use_xi,
                   const float* __restrict__ bias,
                   float* __restrict__ outf,
                   __nv_bfloat16* __restrict__ outhi,
                   __nv_bfloat16* __restrict__ outlo) {
    int gw = (blockIdx.x * blockDim.x + threadIdx.x) >> 5;
    int lane = threadIdx.x & 31;
    if (gw >= NNODES) return;

    float iv = g_invs[gw];
    int self = use_xi ? g_xi[gw] : gw;
    float4 v = *reinterpret_cast<const float4*>(rows + (size_t)self * FDIM + lane * 4);
    float nn = iv * iv;
    float ax = nn * v.x, ay = nn * v.y, az = nn * v.z, aw = nn * v.w;

    int p0 = g_ptr[gw];
    int cnt = g_deg[gw];
    const int2* ap = g_adj + p0;

    int k = 0;
    for (; k + 4 <= cnt; k += 4) {
        int2 e0 = ap[k], e1 = ap[k + 1], e2 = ap[k + 2], e3 = ap[k + 3];
        int r0 = use_xi ? g_xi[e0.x] : e0.x;
        int r1 = use_xi ? g_xi[e1.x] : e1.x;
        int r2 = use_xi ? g_xi[e2.x] : e2.x;
        int r3 = use_xi ? g_xi[e3.x] : e3.x;
        float4 u0 = *reinterpret_cast<const float4*>(rows + (size_t)r0 * FDIM + lane * 4);
        float4 u1 = *reinterpret_cast<const float4*>(rows + (size_t)r1 * FDIM + lane * 4);
        float4 u2 = *reinterpret_cast<const float4*>(rows + (size_t)r2 * FDIM + lane * 4);
        float4 u3 = *reinterpret_cast<const float4*>(rows + (size_t)r3 * FDIM + lane * 4);
        float n0 = __int_as_float(e0.y), n1 = __int_as_float(e1.y);
        float n2 = __int_as_float(e2.y), n3 = __int_as_float(e3.y);
        ax += n0 * u0.x + n1 * u1.x + n2 * u2.x + n3 * u3.x;
        ay += n0 * u0.y + n1 * u1.y + n2 * u2.y + n3 * u3.y;
        az += n0 * u0.z + n1 * u1.z + n2 * u2.z + n3 * u3.z;
        aw += n0 * u0.w + n1 * u1.w + n2 * u2.w + n3 * u3.w;
    }
    for (; k < cnt; k++) {
        int2 e = ap[k];
        int r = use_xi ? g_xi[e.x] : e.x;
        float nk = __int_as_float(e.y);
        float4 u = *reinterpret_cast<const float4*>(rows + (size_t)r * FDIM + lane * 4);
        ax += nk * u.x; ay += nk * u.y; az += nk * u.z; aw += nk * u.w;
    }

    if (bias) {
        float4 b = *reinterpret_cast<const float4*>(bias + lane * 4);
        ax += b.x; ay += b.y; az += b.z; aw += b.w;
    }

    if (outf) {
        *reinterpret_cast<float4*>(outf + (size_t)gw * FDIM + lane * 4) =
            make_float4(ax, ay, az, aw);
    } else {
        uint32_t h0, l0, h1, l1;
        split2(ax, ay, h0, l0);
        split2(az, aw, h1, l1);
        size_t wi = ((size_t)gw * FDIM + lane * 4) >> 1;
        reinterpret_cast<uint2*>(outhi)[wi >> 1] = make_uint2(h0, h1);
        reinterpret_cast<uint2*>(outlo)[wi >> 1] = make_uint2(l0, l1);
    }
}

// ---------------- weight transpose + hi/lo split ----------------
__global__ void wsplit_kernel(const float* __restrict__ W1,
                              const float* __restrict__ W2) {
    int t = blockIdx.x * blockDim.x + threadIdx.x;
    if (t < FDIM * HDIM2) {               // W1: [128][256] -> W1T [256][128]
        int n = t / FDIM, k = t % FDIM;
        float w = W1[(size_t)k * HDIM2 + n];
        __nv_bfloat16 hi = __float2bfloat16(w);
        __nv_bfloat16 lo = __float2bfloat16(w - __bfloat162float(hi));
        g_w1t_hi[(size_t)n * FDIM + k] = hi;
        g_w1t_lo[(size_t)n * FDIM + k] = lo;
    } else if (t < 2 * FDIM * HDIM2) {    // W2: [256][128] -> W2T [128][256]
        int u = t - FDIM * HDIM2;
        int n = u / HDIM2, k = u % HDIM2;
        float w = W2[(size_t)k * FDIM + n];
        __nv_bfloat16 hi = __float2bfloat16(w);
        __nv_bfloat16 lo = __float2bfloat16(w - __bfloat162float(hi));
        g_w2t_hi[(size_t)n * HDIM2 + k] = hi;
        g_w2t_lo[(size_t)n * HDIM2 + k] = lo;
    }
}

// ---------------- split-bf16 HMMA GEMM ----------------
// C[M,Ntot] = (Ahi+Alo)[M,K] @ (BThi+BTlo)[Ntot,K]^T  (+bias)(relu)
// BM=128, BN=64, BK=32; 8 warps 4(m) x 2(n); warp tile 32x32 = 2x4 m16n8k16.
#define STR 56   // smem row stride in bf16
__global__ __launch_bounds__(256)
void gemm_mma_kernel(const __nv_bfloat16* __restrict__ Ahi,
                     const __nv_bfloat16* __restrict__ Alo,
                     const __nv_bfloat16* __restrict__ Bhi,
                     const __nv_bfloat16* __restrict__ Blo,
                     const float* __restrict__ bias,
                     float* __restrict__ outf,
                     __nv_bfloat16* __restrict__ outhi,
                     __nv_bfloat16* __restrict__ outlo,
                     int M, int Ntot, int K, int do_relu) {
    __shared__ __align__(16) __nv_bfloat16 sm[21504];
    const int B_AHI = 0;
    const int B_ALO = 14336;
    const int B_BHI = 28672;
    const int B_BLO = 35840;

    int tid = threadIdx.x;
    int lane = tid & 31;
    int wid = tid >> 5;
    int wm = wid & 3, wn = wid >> 2;
    int row0 = blockIdx.y * 128;
    int n0 = blockIdx.x * 64;
    uint32_t smb = smem_u32(sm);
    char* smc = reinterpret_cast<char*>(sm);

    float acc[2][4][4];
#pragma unroll
    for (int mt = 0; mt < 2; mt++)
#pragma unroll
        for (int nt = 0; nt < 4; nt++)
#pragma unroll
            for (int q = 0; q < 4; q++) acc[mt][nt][q] = 0.f;

    int arow = tid >> 1, ahalf = tid & 1;
    int brow = tid >> 2, bseg = tid & 3;
    int nch = K >> 5;

    for (int c = 0; c < nch; c++) {
        {
            bool v = (row0 + arow) < M;
            size_t off = (size_t)(row0 + arow) * K + c * 32 + ahalf * 16;
            uint4 z = make_uint4(0, 0, 0, 0);
            uint4 h0 = z, h1 = z, l0 = z, l1 = z;
            if (v) {
                h0 = *reinterpret_cast<const uint4*>(Ahi + off);
                h1 = *reinterpret_cast<const uint4*>(Ahi + off + 8);
                l0 = *reinterpret_cast<const uint4*>(Alo + off);
                l1 = *reinterpret_cast<const uint4*>(Alo + off + 8);
            }
            int bo = (arow * STR + ahalf * 16) * 2;
            *reinterpret_cast<uint4*>(smc + B_AHI + bo) = h0;
            *reinterpret_cast<uint4*>(smc + B_AHI + bo + 16) = h1;
            *reinterpret_cast<uint4*>(smc + B_ALO + bo) = l0;
            *reinterpret_cast<uint4*>(smc + B_ALO + bo + 16) = l1;
        }
        {
            size_t off = (size_t)(n0 + brow) * K + c * 32 + bseg * 8;
            uint4 h = *reinterpret_cast<const uint4*>(Bhi + off);
            uint4 l = *reinterpret_cast<const uint4*>(Blo + off);
            int bo = (brow * STR + bseg * 8) * 2;
            *reinterpret_cast<uint4*>(smc + B_BHI + bo) = h;
            *reinterpret_cast<uint4*>(smc + B_BLO + bo) = l;
        }
        __syncthreads();

#pragma unroll
        for (int ks = 0; ks < 2; ks++) {
            uint32_t ah[2][4], al[2][4], bh[4][2], bl[4][2];
#pragma unroll
            for (int mt = 0; mt < 2; mt++) {
                uint32_t ad = smb +
                    ((wm * 32 + mt * 16 + (lane & 15)) * STR +
                     ks * 16 + ((lane >> 4) << 3)) * 2;
                LDSM4(ah[mt], ad + B_AHI);
                LDSM4(al[mt], ad + B_ALO);
            }
#pragma unroll
            for (int nt = 0; nt < 4; nt++) {
                uint32_t bd = smb +
                    ((wn * 32 + nt * 8 + (lane & 7)) * STR +
                     ks * 16 + ((lane >> 3) & 1) * 8) * 2;
                LDSM2(bh[nt], bd + B_BHI);
                LDSM2(bl[nt], bd + B_BLO);
            }
#pragma unroll
            for (int mt = 0; mt < 2; mt++)
#pragma unroll
                for (int nt = 0; nt < 4; nt++) {
                    MMA_BF16(acc[mt][nt], ah[mt], bh[nt]);
                    MMA_BF16(acc[mt][nt], ah[mt], bl[nt]);
                    MMA_BF16(acc[mt][nt], al[mt], bh[nt]);
                }
        }
        __syncthreads();
    }

    int g = lane >> 2, t4 = lane & 3;
#pragma unroll
    for (int mt = 0; mt < 2; mt++) {
        int r0g = row0 + wm * 32 + mt * 16 + g;
#pragma unroll
        for (int nt = 0; nt < 4; nt++) {
            int col = n0 + wn * 32 + nt * 8 + 2 * t4;
            float* a = acc[mt][nt];
            if (bias) {
                float2 bv = *reinterpret_cast<const float2*>(bias + col);
                a[0] += bv.x; a[1] += bv.y; a[2] += bv.x; a[3] += bv.y;
            }
            if (do_relu) {
                a[0] = fmaxf(a[0], 0.f); a[1] = fmaxf(a[1], 0.f);
                a[2] = fmaxf(a[2], 0.f); a[3] = fmaxf(a[3], 0.f);
            }
            if (outf) {
                if (r0g < M)
                    *reinterpret_cast<float2*>(outf + (size_t)r0g * Ntot + col) =
                        make_float2(a[0], a[1]);
                if (r0g + 8 < M)
                    *reinterpret_cast<float2*>(outf + (size_t)(r0g + 8) * Ntot + col) =
                        make_float2(a[2], a[3]);
            }
            if (outhi) {
                uint32_t h, l;
                if (r0g < M) {
                    split2(a[0], a[1], h, l);
                    size_t wi = ((size_t)r0g * Ntot + col) >> 1;
                    reinterpret_cast<uint32_t*>(outhi)[wi] = h;
                    reinterpret_cast<uint32_t*>(outlo)[wi] = l;
                }
                if (r0g + 8 < M) {
                    split2(a[2], a[3], h, l);
                    size_t wi = ((size_t)(r0g + 8) * Ntot + col) >> 1;
                    reinterpret_cast<uint32_t*>(outhi)[wi] = h;
                    reinterpret_cast<uint32_t*>(outlo)[wi] = l;
                }
            }
        }
    }
}

// ---------------- launch ----------------
extern "C" void kernel_launch(void* const* d_in, const int* in_sizes, int n_in,
                              void* d_out, int out_size) {
    const void*  x   = d_in[0];
    const void*  ei  = d_in[1];
    const float* emb = (const float*)d_in[2];   // 4096x128
    const float* W1  = (const float*)d_in[3];   // 128x256
    const float* b1  = (const float*)d_in[4];   // 256
    const float* W2  = (const float*)d_in[5];   // 256x128
    const float* b2  = (const float*)d_in[6];   // 128
    float* out = (float*)d_out;                 // 50000x128

    float* tp;  cudaGetSymbolAddress((void**)&tp, g_t);
    __nv_bfloat16 *ahi, *alo, *h1hi, *h1lo, *w1h, *w1l, *w2h, *w2l;
    cudaGetSymbolAddress((void**)&ahi,  g_ahi);
    cudaGetSymbolAddress((void**)&alo,  g_alo);
    cudaGetSymbolAddress((void**)&h1hi, g_h1hi);
    cudaGetSymbolAddress((void**)&h1lo, g_h1lo);
    cudaGetSymbolAddress((void**)&w1h,  g_w1t_hi);
    cudaGetSymbolAddress((void**)&w1l,  g_w1t_lo);
    cudaGetSymbolAddress((void**)&w2h,  g_w2t_hi);
    cudaGetSymbolAddress((void**)&w2l,  g_w2t_lo);

    // 1) zero deg + dtype detect
    prep1_kernel<<<(NNODES + 255) / 256, 256>>>((const unsigned int*)ei);
    // 2) convert edges + x, degree count
    prep2_kernel<<<(NEDGES + 255) / 256, 256>>>(ei, x);
    // 3) scan degrees -> CSR ptr, invs
    scaninvs_kernel<<<1, 1024>>>();
    // 4) fill CSR adjacency (src, norm)
    fill_kernel<<<(NEDGES + 255) / 256, 256>>>();
    // 5) weight transpose + split
    wsplit_kernel<<<(2 * FDIM * HDIM2 + 255) / 256, 256>>>(W1, W2);
    // 6) gather layer 1 -> A bf16 hi/lo directly
    gather_kernel<<<(NNODES * 32 + 255) / 256, 256>>>(emb, 1, nullptr,
                                                      nullptr, ahi, alo);
    // 7) GEMM1: h1(hi/lo) = relu(A @ W1 + b1)   [M=50000, N=256, K=128]
    {
        dim3 grid(HDIM2 / 64, (NNODES + 127) / 128);
        gemm_mma_kernel<<<grid, 256>>>(ahi, alo, w1h, w1l, b1,
                                       nullptr, h1hi, h1lo,
                                       NNODES, HDIM2, FDIM, 1);
    }
    // 8) GEMM2: t = h1 @ W2                      [M=50000, N=128, K=256]
    {
        dim3 grid(FDIM / 64, (NNODES + 127) / 128);
        gemm_mma_kernel<<<grid, 256>>>(h1hi, h1lo, w2h, w2l, nullptr,
                                       tp, nullptr, nullptr,
                                       NNODES, FDIM, HDIM2, 0);
    }
    // 9) gather layer 2 -> out (self-loop + bias fused)
    gather_kernel<<<(NNODES * 32 + 255) / 256, 256>>>(tp, 0, b2,
                                                      out, nullptr, nullptr);
}

// round 12
// speedup vs baseline: 1.9203x; 1.0791x over previous
#include <cuda_runtime.h>
#include <cuda_bf16.h>
#include <cuda_fp16.h>
#include <cstdint>

#define NNODES 50000
#define NEDGES 800000
#define FDIM   128
#define HDIM2  256

// ---------------- scratch ----------------
__device__ __align__(16) __half g_embh[4096 * FDIM];             // emb as fp16
__device__ __align__(16) __nv_bfloat16 g_ahi[(size_t)NNODES * FDIM];
__device__ __align__(16) __nv_bfloat16 g_alo[(size_t)NNODES * FDIM];
__device__ __align__(16) __nv_bfloat16 g_h1hi[(size_t)NNODES * HDIM2];
__device__ __align__(16) __nv_bfloat16 g_h1lo[(size_t)NNODES * HDIM2];
__device__ __align__(16) __half g_th[(size_t)NNODES * FDIM];     // h1 @ W2 (fp16)
__device__ float g_invs[NNODES];
__device__ int   g_deg[NNODES];
__device__ int   g_ptr[NNODES];
__device__ int   g_cur[NNODES];
__device__ int   g_src[NEDGES];
__device__ int   g_dst[NEDGES];
__device__ __align__(8) int2 g_adj[NEDGES];   // (src, norm-bits) sorted by dst
__device__ int   g_xi[NNODES];
__device__ int   g_not64 = 0;   // 0 -> int64 input, 1 -> int32 (idempotent)
// split transposed weights: W1T [256][128], W2T [128][256]
__device__ __align__(16) __nv_bfloat16 g_w1t_hi[HDIM2 * FDIM];
__device__ __align__(16) __nv_bfloat16 g_w1t_lo[HDIM2 * FDIM];
__device__ __align__(16) __nv_bfloat16 g_w2t_hi[FDIM * HDIM2];
__device__ __align__(16) __nv_bfloat16 g_w2t_lo[FDIM * HDIM2];

// ---------------- helpers ----------------
__device__ __forceinline__ uint32_t smem_u32(const void* p) {
    uint32_t a;
    asm("{ .reg .u64 t; cvta.to.shared.u64 t, %1; cvt.u32.u64 %0, t; }"
        : "=r"(a) : "l"(p));
    return a;
}
__device__ __forceinline__ void split2(float a, float b, uint32_t& h, uint32_t& l) {
    __nv_bfloat162 hb = __float22bfloat162_rn(make_float2(a, b));
    float2 hf = __bfloat1622float2(hb);
    __nv_bfloat162 lb = __float22bfloat162_rn(make_float2(a - hf.x, b - hf.y));
    h = *reinterpret_cast<uint32_t*>(&hb);
    l = *reinterpret_cast<uint32_t*>(&lb);
}

#define LDSM4(r, a) asm volatile( \
    "ldmatrix.sync.aligned.m8n8.x4.shared.b16 {%0,%1,%2,%3}, [%4];" \
    : "=r"((r)[0]), "=r"((r)[1]), "=r"((r)[2]), "=r"((r)[3]) : "r"(a))
#define LDSM2(r, a) asm volatile( \
    "ldmatrix.sync.aligned.m8n8.x2.shared.b16 {%0,%1}, [%2];" \
    : "=r"((r)[0]), "=r"((r)[1]) : "r"(a))
#define MMA_BF16(c, a, b) asm volatile( \
    "mma.sync.aligned.m16n8k16.row.col.f32.bf16.bf16.f32 " \
    "{%0,%1,%2,%3}, {%4,%5,%6,%7}, {%8,%9}, {%0,%1,%2,%3};" \
    : "+f"((c)[0]), "+f"((c)[1]), "+f"((c)[2]), "+f"((c)[3]) \
    : "r"((a)[0]), "r"((a)[1]), "r"((a)[2]), "r"((a)[3]), \
      "r"((b)[0]), "r"((b)[1]))

// ---------------- 1: zero deg + dtype detect ----------------
__global__ void prep1_kernel(const unsigned int* __restrict__ w) {
    int i = blockIdx.x * blockDim.x + threadIdx.x;
    if (i < NNODES) g_deg[i] = 0;
    if (i < 2048) { if (w[2 * i + 1]) g_not64 = 1; }
}

// ---------------- 2: convert edges + x, count degrees ----------------
__global__ void prep2_kernel(const void* __restrict__ ei,
                             const void* __restrict__ x) {
    int e = blockIdx.x * blockDim.x + threadIdx.x;
    int is32 = g_not64;
    if (e < NEDGES) {
        int s, d;
        if (is32) {
            const int* p = (const int*)ei;
            s = p[e]; d = p[NEDGES + e];
        } else {
            const long long* p = (const long long*)ei;
            s = (int)p[e]; d = (int)p[NEDGES + e];
        }
        g_src[e] = s;
        g_dst[e] = d;
        atomicAdd(&g_deg[d], 1);
    }
    if (e < NNODES) {
        g_xi[e] = is32 ? ((const int*)x)[e] : (int)((const long long*)x)[e];
    }
}

// ---------------- 3: exclusive scan of deg -> ptr/cur, and invs ----------------
__global__ __launch_bounds__(1024)
void scaninvs_kernel() {
    __shared__ int part[1024];
    int t = threadIdx.x;
    int lo = t * 49;
    int hi = lo + 49; if (hi > NNODES) hi = NNODES;
    int sum = 0;
    for (int i = lo; i < hi; i++) sum += g_deg[i];
    part[t] = sum;
    __syncthreads();
    for (int off = 1; off < 1024; off <<= 1) {
        int v = (t >= off) ? part[t - off] : 0;
        __syncthreads();
        part[t] += v;
        __syncthreads();
    }
    int base = (t > 0) ? part[t - 1] : 0;
    for (int i = lo; i < hi; i++) {
        g_ptr[i] = base;
        g_cur[i] = base;
        g_invs[i] = rsqrtf((float)g_deg[i] + 1.0f);
        base += g_deg[i];
    }
}

// ---------------- 4: fill CSR adjacency (src, norm) ----------------
__global__ void fill_kernel() {
    int e = blockIdx.x * blockDim.x + threadIdx.x;
    if (e >= NEDGES) return;
    int s = g_src[e];
    int d = g_dst[e];
    float norm = g_invs[s] * g_invs[d];
    int pos = atomicAdd(&g_cur[d], 1);
    g_adj[pos] = make_int2(s, __float_as_int(norm));
}

// ---------------- emb fp32 -> fp16 ----------------
__global__ void emb2h_kernel(const float* __restrict__ emb) {
    int i = blockIdx.x * blockDim.x + threadIdx.x;   // one per 4 floats
    if (i >= 4096 * FDIM / 4) return;
    float4 v = reinterpret_cast<const float4*>(emb)[i];
    __half2 h0 = __float22half2_rn(make_float2(v.x, v.y));
    __half2 h1 = __float22half2_rn(make_float2(v.z, v.w));
    reinterpret_cast<uint2*>(g_embh)[i] =
        make_uint2(*reinterpret_cast<uint32_t*>(&h0),
                   *reinterpret_cast<uint32_t*>(&h1));
}

// ---------------- gather: warp per node, fp16 rows ----------------
// acc = invs^2 * rows[self] + sum_k norm_k * rows[idx_k]  (+bias)
// outhi!=0: write bf16 hi/lo split; else write fp32 to outf.
__global__ __launch_bounds__(256)
void gather_kernel(const __half* __restrict__ rows, int use_xi,
                   const float* __restrict__ bias,
                   float* __restrict__ outf,
                   __nv_bfloat16* __restrict__ outhi,
                   __nv_bfloat16* __restrict__ outlo) {
    int gw = (blockIdx.x * blockDim.x + threadIdx.x) >> 5;
    int lane = threadIdx.x & 31;
    if (gw >= NNODES) return;

    float iv = g_invs[gw];
    int self = use_xi ? g_xi[gw] : gw;
    uint2 sv = *reinterpret_cast<const uint2*>(rows + (size_t)self * FDIM + lane * 4);
    float2 s0 = __half22float2(*reinterpret_cast<__half2*>(&sv.x));
    float2 s1 = __half22float2(*reinterpret_cast<__half2*>(&sv.y));
    float nn = iv * iv;
    float ax = nn * s0.x, ay = nn * s0.y, az = nn * s1.x, aw = nn * s1.y;

    int p0 = g_ptr[gw];
    int cnt = g_deg[gw];
    const int2* ap = g_adj + p0;

    int k = 0;
    for (; k + 8 <= cnt; k += 8) {
        int2 e[8];
#pragma unroll
        for (int j = 0; j < 8; j++) e[j] = ap[k + j];
        int r[8];
#pragma unroll
        for (int j = 0; j < 8; j++) r[j] = use_xi ? g_xi[e[j].x] : e[j].x;
        uint2 u[8];
#pragma unroll
        for (int j = 0; j < 8; j++)
            u[j] = *reinterpret_cast<const uint2*>(rows + (size_t)r[j] * FDIM + lane * 4);
#pragma unroll
        for (int j = 0; j < 8; j++) {
            float nk = __int_as_float(e[j].y);
            float2 f0 = __half22float2(*reinterpret_cast<__half2*>(&u[j].x));
            float2 f1 = __half22float2(*reinterpret_cast<__half2*>(&u[j].y));
            ax += nk * f0.x; ay += nk * f0.y; az += nk * f1.x; aw += nk * f1.y;
        }
    }
    for (; k < cnt; k++) {
        int2 e = ap[k];
        int r = use_xi ? g_xi[e.x] : e.x;
        float nk = __int_as_float(e.y);
        uint2 u = *reinterpret_cast<const uint2*>(rows + (size_t)r * FDIM + lane * 4);
        float2 f0 = __half22float2(*reinterpret_cast<__half2*>(&u.x));
        float2 f1 = __half22float2(*reinterpret_cast<__half2*>(&u.y));
        ax += nk * f0.x; ay += nk * f0.y; az += nk * f1.x; aw += nk * f1.y;
    }

    if (bias) {
        float4 b = *reinterpret_cast<const float4*>(bias + lane * 4);
        ax += b.x; ay += b.y; az += b.z; aw += b.w;
    }

    if (outf) {
        *reinterpret_cast<float4*>(outf + (size_t)gw * FDIM + lane * 4) =
            make_float4(ax, ay, az, aw);
    } else {
        uint32_t h0, l0, h1, l1;
        split2(ax, ay, h0, l0);
        split2(az, aw, h1, l1);
        size_t wi = ((size_t)gw * FDIM + lane * 4) >> 2;   // uint2 index (4 bf16)
        reinterpret_cast<uint2*>(outhi)[wi] = make_uint2(h0, h1);
        reinterpret_cast<uint2*>(outlo)[wi] = make_uint2(l0, l1);
    }
}

// ---------------- weight transpose + hi/lo split ----------------
__global__ void wsplit_kernel(const float* __restrict__ W1,
                              const float* __restrict__ W2) {
    int t = blockIdx.x * blockDim.x + threadIdx.x;
    if (t < FDIM * HDIM2) {               // W1: [128][256] -> W1T [256][128]
        int n = t / FDIM, k = t % FDIM;
        float w = W1[(size_t)k * HDIM2 + n];
        __nv_bfloat16 hi = __float2bfloat16(w);
        __nv_bfloat16 lo = __float2bfloat16(w - __bfloat162float(hi));
        g_w1t_hi[(size_t)n * FDIM + k] = hi;
        g_w1t_lo[(size_t)n * FDIM + k] = lo;
    } else if (t < 2 * FDIM * HDIM2) {    // W2: [256][128] -> W2T [128][256]
        int u = t - FDIM * HDIM2;
        int n = u / HDIM2, k = u % HDIM2;
        float w = W2[(size_t)k * FDIM + n];
        __nv_bfloat16 hi = __float2bfloat16(w);
        __nv_bfloat16 lo = __float2bfloat16(w - __bfloat162float(hi));
        g_w2t_hi[(size_t)n * HDIM2 + k] = hi;
        g_w2t_lo[(size_t)n * HDIM2 + k] = lo;
    }
}

// ---------------- split-bf16 HMMA GEMM ----------------
// BM=128, BN=64, BK=32; 8 warps 4(m) x 2(n); warp tile 32x32 = 2x4 m16n8k16.
#define STR 56   // smem row stride in bf16
__global__ __launch_bounds__(256)
void gemm_mma_kernel(const __nv_bfloat16* __restrict__ Ahi,
                     const __nv_bfloat16* __restrict__ Alo,
                     const __nv_bfloat16* __restrict__ Bhi,
                     const __nv_bfloat16* __restrict__ Blo,
                     const float* __restrict__ bias,
                     __half* __restrict__ outh,
                     __nv_bfloat16* __restrict__ outhi,
                     __nv_bfloat16* __restrict__ outlo,
                     int M, int Ntot, int K, int do_relu) {
    __shared__ __align__(16) __nv_bfloat16 sm[21504];
    const int B_AHI = 0;
    const int B_ALO = 14336;
    const int B_BHI = 28672;
    const int B_BLO = 35840;

    int tid = threadIdx.x;
    int lane = tid & 31;
    int wid = tid >> 5;
    int wm = wid & 3, wn = wid >> 2;
    int row0 = blockIdx.y * 128;
    int n0 = blockIdx.x * 64;
    uint32_t smb = smem_u32(sm);
    char* smc = reinterpret_cast<char*>(sm);

    float acc[2][4][4];
#pragma unroll
    for (int mt = 0; mt < 2; mt++)
#pragma unroll
        for (int nt = 0; nt < 4; nt++)
#pragma unroll
            for (int q = 0; q < 4; q++) acc[mt][nt][q] = 0.f;

    int arow = tid >> 1, ahalf = tid & 1;
    int brow = tid >> 2, bseg = tid & 3;
    int nch = K >> 5;

    for (int c = 0; c < nch; c++) {
        {
            bool v = (row0 + arow) < M;
            size_t off = (size_t)(row0 + arow) * K + c * 32 + ahalf * 16;
            uint4 z = make_uint4(0, 0, 0, 0);
            uint4 h0 = z, h1 = z, l0 = z, l1 = z;
            if (v) {
                h0 = *reinterpret_cast<const uint4*>(Ahi + off);
                h1 = *reinterpret_cast<const uint4*>(Ahi + off + 8);
                l0 = *reinterpret_cast<const uint4*>(Alo + off);
                l1 = *reinterpret_cast<const uint4*>(Alo + off + 8);
            }
            int bo = (arow * STR + ahalf * 16) * 2;
            *reinterpret_cast<uint4*>(smc + B_AHI + bo) = h0;
            *reinterpret_cast<uint4*>(smc + B_AHI + bo + 16) = h1;
            *reinterpret_cast<uint4*>(smc + B_ALO + bo) = l0;
            *reinterpret_cast<uint4*>(smc + B_ALO + bo + 16) = l1;
        }
        {
            size_t off = (size_t)(n0 + brow) * K + c * 32 + bseg * 8;
            uint4 h = *reinterpret_cast<const uint4*>(Bhi + off);
            uint4 l = *reinterpret_cast<const uint4*>(Blo + off);
            int bo = (brow * STR + bseg * 8) * 2;
            *reinterpret_cast<uint4*>(smc + B_BHI + bo) = h;
            *reinterpret_cast<uint4*>(smc + B_BLO + bo) = l;
        }
        __syncthreads();

#pragma unroll
        for (int ks = 0; ks < 2; ks++) {
            uint32_t ah[2][4], al[2][4], bh[4][2], bl[4][2];
#pragma unroll
            for (int mt = 0; mt < 2; mt++) {
                uint32_t ad = smb +
                    ((wm * 32 + mt * 16 + (lane & 15)) * STR +
                     ks * 16 + ((lane >> 4) << 3)) * 2;
                LDSM4(ah[mt], ad + B_AHI);
                LDSM4(al[mt], ad + B_ALO);
            }
#pragma unroll
            for (int nt = 0; nt < 4; nt++) {
                uint32_t bd = smb +
                    ((wn * 32 + nt * 8 + (lane & 7)) * STR +
                     ks * 16 + ((lane >> 3) & 1) * 8) * 2;
                LDSM2(bh[nt], bd + B_BHI);
                LDSM2(bl[nt], bd + B_BLO);
            }
#pragma unroll
            for (int mt = 0; mt < 2; mt++)
#pragma unroll
                for (int nt = 0; nt < 4; nt++) {
                    MMA_BF16(acc[mt][nt], ah[mt], bh[nt]);
                    MMA_BF16(acc[mt][nt], ah[mt], bl[nt]);
                    MMA_BF16(acc[mt][nt], al[mt], bh[nt]);
                }
        }
        __syncthreads();
    }

    int g = lane >> 2, t4 = lane & 3;
#pragma unroll
    for (int mt = 0; mt < 2; mt++) {
        int r0g = row0 + wm * 32 + mt * 16 + g;
#pragma unroll
        for (int nt = 0; nt < 4; nt++) {
            int col = n0 + wn * 32 + nt * 8 + 2 * t4;
            float* a = acc[mt][nt];
            if (bias) {
                float2 bv = *reinterpret_cast<const float2*>(bias + col);
                a[0] += bv.x; a[1] += bv.y; a[2] += bv.x; a[3] += bv.y;
            }
            if (do_relu) {
                a[0] = fmaxf(a[0], 0.f); a[1] = fmaxf(a[1], 0.f);
                a[2] = fmaxf(a[2], 0.f); a[3] = fmaxf(a[3], 0.f);
            }
            if (outh) {   // fp16 output
                if (r0g < M) {
                    __half2 h = __float22half2_rn(make_float2(a[0], a[1]));
                    reinterpret_cast<uint32_t*>(outh)[((size_t)r0g * Ntot + col) >> 1] =
                        *reinterpret_cast<uint32_t*>(&h);
                }
                if (r0g + 8 < M) {
                    __half2 h = __float22half2_rn(make_float2(a[2], a[3]));
                    reinterpret_cast<uint32_t*>(outh)[((size_t)(r0g + 8) * Ntot + col) >> 1] =
                        *reinterpret_cast<uint32_t*>(&h);
                }
            }
            if (outhi) {  // bf16 hi/lo split output
                uint32_t h, l;
                if (r0g < M) {
                    split2(a[0], a[1], h, l);
                    size_t wi = ((size_t)r0g * Ntot + col) >> 1;
                    reinterpret_cast<uint32_t*>(outhi)[wi] = h;
                    reinterpret_cast<uint32_t*>(outlo)[wi] = l;
                }
                if (r0g + 8 < M) {
                    split2(a[2], a[3], h, l);
                    size_t wi = ((size_t)(r0g + 8) * Ntot + col) >> 1;
                    reinterpret_cast<uint32_t*>(outhi)[wi] = h;
                    reinterpret_cast<uint32_t*>(outlo)[wi] = l;
                }
            }
        }
    }
}

// ---------------- launch ----------------
extern "C" void kernel_launch(void* const* d_in, const int* in_sizes, int n_in,
                              void* d_out, int out_size) {
    const void*  x   = d_in[0];
    const void*  ei  = d_in[1];
    const float* emb = (const float*)d_in[2];   // 4096x128
    const float* W1  = (const float*)d_in[3];   // 128x256
    const float* b1  = (const float*)d_in[4];   // 256
    const float* W2  = (const float*)d_in[5];   // 256x128
    const float* b2  = (const float*)d_in[6];   // 128
    float* out = (float*)d_out;                 // 50000x128

    __half *embh, *th;
    cudaGetSymbolAddress((void**)&embh, g_embh);
    cudaGetSymbolAddress((void**)&th,   g_th);
    __nv_bfloat16 *ahi, *alo, *h1hi, *h1lo, *w1h, *w1l, *w2h, *w2l;
    cudaGetSymbolAddress((void**)&ahi,  g_ahi);
    cudaGetSymbolAddress((void**)&alo,  g_alo);
    cudaGetSymbolAddress((void**)&h1hi, g_h1hi);
    cudaGetSymbolAddress((void**)&h1lo, g_h1lo);
    cudaGetSymbolAddress((void**)&w1h,  g_w1t_hi);
    cudaGetSymbolAddress((void**)&w1l,  g_w1t_lo);
    cudaGetSymbolAddress((void**)&w2h,  g_w2t_hi);
    cudaGetSymbolAddress((void**)&w2l,  g_w2t_lo);

    // 1) zero deg + dtype detect
    prep1_kernel<<<(NNODES + 255) / 256, 256>>>((const unsigned int*)ei);
    // 2) convert edges + x, degree count
    prep2_kernel<<<(NEDGES + 255) / 256, 256>>>(ei, x);
    // 3) scan degrees -> CSR ptr, invs
    scaninvs_kernel<<<1, 1024>>>();
    // 4) fill CSR adjacency (src, norm)   <-- ncu capture slot
    fill_kernel<<<(NEDGES + 255) / 256, 256>>>();
    // 5) emb -> fp16
    emb2h_kernel<<<(4096 * FDIM / 4 + 255) / 256, 256>>>(emb);
    // 6) weight transpose + split
    wsplit_kernel<<<(2 * FDIM * HDIM2 + 255) / 256, 256>>>(W1, W2);
    // 7) gather layer 1 (fp16 rows) -> A bf16 hi/lo
    gather_kernel<<<(NNODES * 32 + 255) / 256, 256>>>(embh, 1, nullptr,
                                                      nullptr, ahi, alo);
    // 8) GEMM1: h1(hi/lo) = relu(A @ W1 + b1)   [M=50000, N=256, K=128]
    {
        dim3 grid(HDIM2 / 64, (NNODES + 127) / 128);
        gemm_mma_kernel<<<grid, 256>>>(ahi, alo, w1h, w1l, b1,
                                       nullptr, h1hi, h1lo,
                                       NNODES, HDIM2, FDIM, 1);
    }
    // 9) GEMM2: t(fp16) = h1 @ W2               [M=50000, N=128, K=256]
    {
        dim3 grid(FDIM / 64, (NNODES + 127) / 128);
        gemm_mma_kernel<<<grid, 256>>>(h1hi, h1lo, w2h, w2l, nullptr,
                                       th, nullptr, nullptr,
                                       NNODES, FDIM, HDIM2, 0);
    }
    // 10) gather layer 2 (fp16 rows) -> out fp32 (self-loop + bias fused)
    gather_kernel<<<(NNODES * 32 + 255) / 256, 256>>>(th, 0, b2,
                                                      out, nullptr, nullptr);
}

// round 14
// speedup vs baseline: 2.2650x; 1.1795x over previous
#include <cuda_runtime.h>
#include <cuda_fp16.h>
#include <cstdint>

#define NNODES 50000
#define NEDGES 800000
#define FDIM   128
#define HDIM2  256

// ---------------- scratch ----------------
__device__ __align__(16) __half g_embh[4096 * FDIM];             // emb as fp16
__device__ __align__(16) __half g_ah[(size_t)NNODES * FDIM];     // A_hat*E[x] fp16
__device__ __align__(16) __half g_h1h[(size_t)NNODES * HDIM2];   // h1 fp16
__device__ __align__(16) __half g_th[(size_t)NNODES * FDIM];     // h1 @ W2 fp16
__device__ float g_invs[NNODES];
__device__ int   g_deg[NNODES];
__device__ int   g_ptr[NNODES];
__device__ int   g_cur[NNODES];
__device__ int   g_src[NEDGES];
__device__ int   g_dst[NEDGES];
__device__ __align__(8) int2 g_adj[NEDGES];   // (src, norm-bits) sorted by dst
__device__ int   g_xi[NNODES];
__device__ int   g_not64 = 0;   // 0 -> int64 input, 1 -> int32 (idempotent)
// fp16 transposed weights: W1T [256][128], W2T [128][256]
__device__ __align__(16) __half g_w1t[HDIM2 * FDIM];
__device__ __align__(16) __half g_w2t[FDIM * HDIM2];

// ---------------- helpers ----------------
__device__ __forceinline__ uint32_t smem_u32(const void* p) {
    uint32_t a;
    asm("{ .reg .u64 t; cvta.to.shared.u64 t, %1; cvt.u32.u64 %0, t; }"
        : "=r"(a) : "l"(p));
    return a;
}

#define LDSM4(r, a) asm volatile( \
    "ldmatrix.sync.aligned.m8n8.x4.shared.b16 {%0,%1,%2,%3}, [%4];" \
    : "=r"((r)[0]), "=r"((r)[1]), "=r"((r)[2]), "=r"((r)[3]) : "r"(a))
#define LDSM2(r, a) asm volatile( \
    "ldmatrix.sync.aligned.m8n8.x2.shared.b16 {%0,%1}, [%2];" \
    : "=r"((r)[0]), "=r"((r)[1]) : "r"(a))
#define MMA_F16(c, a, b) asm volatile( \
    "mma.sync.aligned.m16n8k16.row.col.f32.f16.f16.f32 " \
    "{%0,%1,%2,%3}, {%4,%5,%6,%7}, {%8,%9}, {%0,%1,%2,%3};" \
    : "+f"((c)[0]), "+f"((c)[1]), "+f"((c)[2]), "+f"((c)[3]) \
    : "r"((a)[0]), "r"((a)[1]), "r"((a)[2]), "r"((a)[3]), \
      "r"((b)[0]), "r"((b)[1]))

// ---------------- 1: zero deg + dtype detect ----------------
__global__ void prep1_kernel(const unsigned int* __restrict__ w) {
    int i = blockIdx.x * blockDim.x + threadIdx.x;
    if (i < NNODES) g_deg[i] = 0;
    if (i < 2048) { if (w[2 * i + 1]) g_not64 = 1; }
}

// ---------------- 2: convert edges + x, count degrees ----------------
__global__ void prep2_kernel(const void* __restrict__ ei,
                             const void* __restrict__ x) {
    int e = blockIdx.x * blockDim.x + threadIdx.x;
    int is32 = g_not64;
    if (e < NEDGES) {
        int s, d;
        if (is32) {
            const int* p = (const int*)ei;
            s = p[e]; d = p[NEDGES + e];
        } else {
            const long long* p = (const long long*)ei;
            s = (int)p[e]; d = (int)p[NEDGES + e];
        }
        g_src[e] = s;
        g_dst[e] = d;
        atomicAdd(&g_deg[d], 1);
    }
    if (e < NNODES) {
        g_xi[e] = is32 ? ((const int*)x)[e] : (int)((const long long*)x)[e];
    }
}

// ---------------- 3: exclusive scan of deg -> ptr/cur, and invs ----------------
__global__ __launch_bounds__(1024)
void scaninvs_kernel() {
    __shared__ int part[1024];
    int t = threadIdx.x;
    int lo = t * 49;
    int hi = lo + 49; if (hi > NNODES) hi = NNODES;
    int sum = 0;
    for (int i = lo; i < hi; i++) sum += g_deg[i];
    part[t] = sum;
    __syncthreads();
    for (int off = 1; off < 1024; off <<= 1) {
        int v = (t >= off) ? part[t - off] : 0;
        __syncthreads();
        part[t] += v;
        __syncthreads();
    }
    int base = (t > 0) ? part[t - 1] : 0;
    for (int i = lo; i < hi; i++) {
        g_ptr[i] = base;
        g_cur[i] = base;
        g_invs[i] = rsqrtf((float)g_deg[i] + 1.0f);
        base += g_deg[i];
    }
}

// ---------------- 4: fill CSR adjacency (src, norm) ----------------
__global__ void fill_kernel() {
    int e = blockIdx.x * blockDim.x + threadIdx.x;
    if (e >= NEDGES) return;
    int s = g_src[e];
    int d = g_dst[e];
    float norm = g_invs[s] * g_invs[d];
    int pos = atomicAdd(&g_cur[d], 1);
    g_adj[pos] = make_int2(s, __float_as_int(norm));
}

// ---------------- emb fp32 -> fp16 ----------------
__global__ void emb2h_kernel(const float* __restrict__ emb) {
    int i = blockIdx.x * blockDim.x + threadIdx.x;   // one per 4 floats
    if (i >= 4096 * FDIM / 4) return;
    float4 v = reinterpret_cast<const float4*>(emb)[i];
    __half2 h0 = __float22half2_rn(make_float2(v.x, v.y));
    __half2 h1 = __float22half2_rn(make_float2(v.z, v.w));
    reinterpret_cast<uint2*>(g_embh)[i] =
        make_uint2(*reinterpret_cast<uint32_t*>(&h0),
                   *reinterpret_cast<uint32_t*>(&h1));
}

// ---------------- weight transpose fp16 ----------------
__global__ void wt_kernel(const float* __restrict__ W1,
                          const float* __restrict__ W2) {
    int t = blockIdx.x * blockDim.x + threadIdx.x;
    if (t < FDIM * HDIM2) {               // W1: [128][256] -> W1T [256][128]
        int n = t / FDIM, k = t % FDIM;
        g_w1t[(size_t)n * FDIM + k] = __float2half(W1[(size_t)k * HDIM2 + n]);
    } else if (t < 2 * FDIM * HDIM2) {    // W2: [256][128] -> W2T [128][256]
        int u = t - FDIM * HDIM2;
        int n = u / HDIM2, k = u % HDIM2;
        g_w2t[(size_t)n * HDIM2 + k] = __float2half(W2[(size_t)k * FDIM + n]);
    }
}

// ---------------- gather: warp per node, 2 neighbors per warp-instruction ----
// 16-lane halves; each lane loads uint4 = 8 fp16 (16 B). halves take
// alternating CSR entries; merged by shfl_xor(16) at the end.
__device__ __forceinline__ void fma8(float* a, uint4 u, float nk) {
    const __half2* h = reinterpret_cast<const __half2*>(&u);
#pragma unroll
    for (int q = 0; q < 4; q++) {
        float2 f = __half22float2(h[q]);
        a[2 * q]     += nk * f.x;
        a[2 * q + 1] += nk * f.y;
    }
}

__global__ __launch_bounds__(256)
void gather_kernel(const __half* __restrict__ rows, int use_xi,
                   const float* __restrict__ bias,
                   float* __restrict__ outf,
                   __half* __restrict__ outh) {
    int gw = (blockIdx.x * blockDim.x + threadIdx.x) >> 5;
    int lane = threadIdx.x & 31;
    if (gw >= NNODES) return;
    int half = lane >> 4, sub = lane & 15;

    float a[8];
#pragma unroll
    for (int j = 0; j < 8; j++) a[j] = 0.f;

    float iv = g_invs[gw];
    int p0 = g_ptr[gw];
    int cnt = g_deg[gw];
    const int2* ap = g_adj + p0;

    // self-loop term: half 0 only
    if (half == 0) {
        int self = use_xi ? g_xi[gw] : gw;
        uint4 u = *reinterpret_cast<const uint4*>(rows + (size_t)self * FDIM + sub * 8);
        fma8(a, u, iv * iv);
    }

    int k = half;
    for (; k + 6 < cnt; k += 8) {
        int2 e0 = ap[k], e1 = ap[k + 2], e2 = ap[k + 4], e3 = ap[k + 6];
        int r0 = use_xi ? g_xi[e0.x] : e0.x;
        int r1 = use_xi ? g_xi[e1.x] : e1.x;
        int r2 = use_xi ? g_xi[e2.x] : e2.x;
        int r3 = use_xi ? g_xi[e3.x] : e3.x;
        uint4 u0 = *reinterpret_cast<const uint4*>(rows + (size_t)r0 * FDIM + sub * 8);
        uint4 u1 = *reinterpret_cast<const uint4*>(rows + (size_t)r1 * FDIM + sub * 8);
        uint4 u2 = *reinterpret_cast<const uint4*>(rows + (size_t)r2 * FDIM + sub * 8);
        uint4 u3 = *reinterpret_cast<const uint4*>(rows + (size_t)r3 * FDIM + sub * 8);
        fma8(a, u0, __int_as_float(e0.y));
        fma8(a, u1, __int_as_float(e1.y));
        fma8(a, u2, __int_as_float(e2.y));
        fma8(a, u3, __int_as_float(e3.y));
    }
    for (; k < cnt; k += 2) {
        int2 e = ap[k];
        int r = use_xi ? g_xi[e.x] : e.x;
        uint4 u = *reinterpret_cast<const uint4*>(rows + (size_t)r * FDIM + sub * 8);
        fma8(a, u, __int_as_float(e.y));
    }

    // merge halves
#pragma unroll
    for (int j = 0; j < 8; j++)
        a[j] += __shfl_xor_sync(0xffffffffu, a[j], 16);

    if (lane < 16) {
        if (outf) {
            float4 b0 = *reinterpret_cast<const float4*>(bias + sub * 8);
            float4 b1 = *reinterpret_cast<const float4*>(bias + sub * 8 + 4);
            float4 o0 = make_float4(a[0] + b0.x, a[1] + b0.y, a[2] + b0.z, a[3] + b0.w);
            float4 o1 = make_float4(a[4] + b1.x, a[5] + b1.y, a[6] + b1.z, a[7] + b1.w);
            float* op = outf + (size_t)gw * FDIM + sub * 8;
            *reinterpret_cast<float4*>(op) = o0;
            *reinterpret_cast<float4*>(op + 4) = o1;
        } else {
            uint32_t w[4];
#pragma unroll
            for (int q = 0; q < 4; q++) {
                __half2 h = __float22half2_rn(make_float2(a[2 * q], a[2 * q + 1]));
                w[q] = *reinterpret_cast<uint32_t*>(&h);
            }
            *reinterpret_cast<uint4*>(outh + (size_t)gw * FDIM + sub * 8) =
                make_uint4(w[0], w[1], w[2], w[3]);
        }
    }
}

// ---------------- fp16 HMMA GEMM ----------------
// C[M,Ntot] = A[M,K] @ BT[Ntot,K]^T  (+bias)(relu), fp32 accum, fp16 out
// BM=128, BN=64, BK=32; 8 warps 4(m) x 2(n); warp tile 32x32 = 2x4 m16n8k16.
#define STR 56   // smem row stride in fp16
__global__ __launch_bounds__(256)
void gemm_f16_kernel(const __half* __restrict__ A,
                     const __half* __restrict__ BT,
                     const float* __restrict__ bias,
                     __half* __restrict__ outh,
                     int M, int Ntot, int K, int do_relu) {
    __shared__ __align__(16) __half sm[10752];   // 21504 B
    const int B_A = 0;               // bytes
    const int B_B = 14336;           // 128*56*2

    int tid = threadIdx.x;
    int lane = tid & 31;
    int wid = tid >> 5;
    int wm = wid & 3, wn = wid >> 2;
    int row0 = blockIdx.y * 128;
    int n0 = blockIdx.x * 64;
    uint32_t smb = smem_u32(sm);
    char* smc = reinterpret_cast<char*>(sm);

    float acc[2][4][4];
#pragma unroll
    for (int mt = 0; mt < 2; mt++)
#pragma unroll
        for (int nt = 0; nt < 4; nt++)
#pragma unroll
            for (int q = 0; q < 4; q++) acc[mt][nt][q] = 0.f;

    int arow = tid >> 1, ahalf = tid & 1;     // A: 2 threads/row, 16 fp16 each
    int brow = tid >> 2, bseg = tid & 3;      // B: 4 threads/row, 8 fp16 each
    int nch = K >> 5;

    for (int c = 0; c < nch; c++) {
        {
            bool v = (row0 + arow) < M;
            size_t off = (size_t)(row0 + arow) * K + c * 32 + ahalf * 16;
            uint4 z = make_uint4(0, 0, 0, 0);
            uint4 h0 = z, h1 = z;
            if (v) {
                h0 = *reinterpret_cast<const uint4*>(A + off);
                h1 = *reinterpret_cast<const uint4*>(A + off + 8);
            }
            int bo = (arow * STR + ahalf * 16) * 2;
            *reinterpret_cast<uint4*>(smc + B_A + bo) = h0;
            *reinterpret_cast<uint4*>(smc + B_A + bo + 16) = h1;
        }
        {
            size_t off = (size_t)(n0 + brow) * K + c * 32 + bseg * 8;
            uint4 h = *reinterpret_cast<const uint4*>(BT + off);
            int bo = (brow * STR + bseg * 8) * 2;
            *reinterpret_cast<uint4*>(smc + B_B + bo) = h;
        }
        __syncthreads();

#pragma unroll
        for (int ks = 0; ks < 2; ks++) {
            uint32_t ah[2][4], bh[4][2];
#pragma unroll
            for (int mt = 0; mt < 2; mt++) {
                uint32_t ad = smb +
                    ((wm * 32 + mt * 16 + (lane & 15)) * STR +
                     ks * 16 + ((lane >> 4) << 3)) * 2;
                LDSM4(ah[mt], ad + B_A);
            }
#pragma unroll
            for (int nt = 0; nt < 4; nt++) {
                uint32_t bd = smb +
                    ((wn * 32 + nt * 8 + (lane & 7)) * STR +
                     ks * 16 + ((lane >> 3) & 1) * 8) * 2;
                LDSM2(bh[nt], bd + B_B);
            }
#pragma unroll
            for (int mt = 0; mt < 2; mt++)
#pragma unroll
                for (int nt = 0; nt < 4; nt++)
                    MMA_F16(acc[mt][nt], ah[mt], bh[nt]);
        }
        __syncthreads();
    }

    int g = lane >> 2, t4 = lane & 3;
#pragma unroll
    for (int mt = 0; mt < 2; mt++) {
        int r0g = row0 + wm * 32 + mt * 16 + g;
#pragma unroll
        for (int nt = 0; nt < 4; nt++) {
            int col = n0 + wn * 32 + nt * 8 + 2 * t4;
            float* a = acc[mt][nt];
            if (bias) {
                float2 bv = *reinterpret_cast<const float2*>(bias + col);
                a[0] += bv.x; a[1] += bv.y; a[2] += bv.x; a[3] += bv.y;
            }
            if (do_relu) {
                a[0] = fmaxf(a[0], 0.f); a[1] = fmaxf(a[1], 0.f);
                a[2] = fmaxf(a[2], 0.f); a[3] = fmaxf(a[3], 0.f);
            }
            if (r0g < M) {
                __half2 h = __float22half2_rn(make_float2(a[0], a[1]));
                reinterpret_cast<uint32_t*>(outh)[((size_t)r0g * Ntot + col) >> 1] =
                    *reinterpret_cast<uint32_t*>(&h);
            }
            if (r0g + 8 < M) {
                __half2 h = __float22half2_rn(make_float2(a[2], a[3]));
                reinterpret_cast<uint32_t*>(outh)[((size_t)(r0g + 8) * Ntot + col) >> 1] =
                    *reinterpret_cast<uint32_t*>(&h);
            }
        }
    }
}

// ---------------- launch ----------------
extern "C" void kernel_launch(void* const* d_in, const int* in_sizes, int n_in,
                              void* d_out, int out_size) {
    const void*  x   = d_in[0];
    const void*  ei  = d_in[1];
    const float* emb = (const float*)d_in[2];   // 4096x128
    const float* W1  = (const float*)d_in[3];   // 128x256
    const float* b1  = (const float*)d_in[4];   // 256
    const float* W2  = (const float*)d_in[5];   // 256x128
    const float* b2  = (const float*)d_in[6];   // 128
    float* out = (float*)d_out;                 // 50000x128

    __half *embh, *ah, *h1h, *th, *w1t, *w2t;
    cudaGetSymbolAddress((void**)&embh, g_embh);
    cudaGetSymbolAddress((void**)&ah,   g_ah);
    cudaGetSymbolAddress((void**)&h1h,  g_h1h);
    cudaGetSymbolAddress((void**)&th,   g_th);
    cudaGetSymbolAddress((void**)&w1t,  g_w1t);
    cudaGetSymbolAddress((void**)&w2t,  g_w2t);

    // 1) zero deg + dtype detect
    prep1_kernel<<<(NNODES + 255) / 256, 256>>>((const unsigned int*)ei);
    // 2) convert edges + x, degree count
    prep2_kernel<<<(NEDGES + 255) / 256, 256>>>(ei, x);
    // 3) scan degrees -> CSR ptr, invs
    scaninvs_kernel<<<1, 1024>>>();
    // 4) fill CSR adjacency (src, norm)   <-- ncu capture slot
    fill_kernel<<<(NEDGES + 255) / 256, 256>>>();
    // 5) emb -> fp16
    emb2h_kernel<<<(4096 * FDIM / 4 + 255) / 256, 256>>>(emb);
    // 6) weight transpose fp16
    wt_kernel<<<(2 * FDIM * HDIM2 + 255) / 256, 256>>>(W1, W2);
    // 7) gather layer 1 (fp16 rows) -> A fp16
    gather_kernel<<<(NNODES * 32 + 255) / 256, 256>>>(embh, 1, nullptr,
                                                      nullptr, ah);
    // 8) GEMM1: h1 = relu(A @ W1 + b1)   [M=50000, N=256, K=128]
    {
        dim3 grid(HDIM2 / 64, (NNODES + 127) / 128);
        gemm_f16_kernel<<<grid, 256>>>(ah, w1t, b1, h1h,
                                       NNODES, HDIM2, FDIM, 1);
    }
    // 9) GEMM2: t = h1 @ W2              [M=50000, N=128, K=256]
    {
        dim3 grid(FDIM / 64, (NNODES + 127) / 128);
        gemm_f16_kernel<<<grid, 256>>>(h1h, w2t, nullptr, th,
                                       NNODES, FDIM, HDIM2, 0);
    }
    // 10) gather layer 2 (fp16 rows) -> out fp32 (self-loop + bias fused)
    gather_kernel<<<(NNODES * 32 + 255) / 256, 256>>>(th, 0, b2,
                                                      out, nullptr);
}

// round 15
// speedup vs baseline: 2.3166x; 1.0228x over previous
#include <cuda_runtime.h>
#include <cuda_fp16.h>
#include <cstdint>

#define NNODES 50000
#define NEDGES 800000
#define FDIM   128
#define HDIM2  256

// ---------------- scratch ----------------
__device__ __align__(16) __half g_embh[4096 * FDIM];             // emb as fp16
__device__ __align__(16) __half g_ah[(size_t)NNODES * FDIM];     // A_hat*E[x] fp16
__device__ __align__(16) __half g_h1h[(size_t)NNODES * HDIM2];   // h1 fp16
__device__ __align__(16) __half g_th[(size_t)NNODES * FDIM];     // h1 @ W2 fp16
__device__ float g_invs[NNODES];
__device__ int   g_deg[NNODES];
__device__ int   g_ptr[NNODES];
__device__ int   g_cur[NNODES];
__device__ __align__(8) int2 g_adj1[NEDGES];  // (xi[src], norm) sorted by dst
__device__ __align__(8) int2 g_adj2[NEDGES];  // (src,     norm) sorted by dst
__device__ int   g_xi[NNODES];
__device__ int   g_not64 = 0;   // 0 -> int64 input, 1 -> int32 (idempotent)
// fp16 transposed weights: W1T [256][128], W2T [128][256]
__device__ __align__(16) __half g_w1t[HDIM2 * FDIM];
__device__ __align__(16) __half g_w2t[FDIM * HDIM2];

// ---------------- helpers ----------------
__device__ __forceinline__ uint32_t smem_u32(const void* p) {
    uint32_t a;
    asm("{ .reg .u64 t; cvta.to.shared.u64 t, %1; cvt.u32.u64 %0, t; }"
        : "=r"(a) : "l"(p));
    return a;
}

#define LDSM4(r, a) asm volatile( \
    "ldmatrix.sync.aligned.m8n8.x4.shared.b16 {%0,%1,%2,%3}, [%4];" \
    : "=r"((r)[0]), "=r"((r)[1]), "=r"((r)[2]), "=r"((r)[3]) : "r"(a))
#define LDSM2(r, a) asm volatile( \
    "ldmatrix.sync.aligned.m8n8.x2.shared.b16 {%0,%1}, [%2];" \
    : "=r"((r)[0]), "=r"((r)[1]) : "r"(a))
#define MMA_F16(c, a, b) asm volatile( \
    "mma.sync.aligned.m16n8k16.row.col.f32.f16.f16.f32 " \
    "{%0,%1,%2,%3}, {%4,%5,%6,%7}, {%8,%9}, {%0,%1,%2,%3};" \
    : "+f"((c)[0]), "+f"((c)[1]), "+f"((c)[2]), "+f"((c)[3]) \
    : "r"((a)[0]), "r"((a)[1]), "r"((a)[2]), "r"((a)[3]), \
      "r"((b)[0]), "r"((b)[1]))

__device__ __forceinline__ int ld_edge(const void* ei, int is32, int idx) {
    return is32 ? ((const int*)ei)[idx] : (int)((const long long*)ei)[idx];
}

// ---------------- 1: zero deg + dtype detect ----------------
__global__ void prep1_kernel(const unsigned int* __restrict__ w) {
    int i = blockIdx.x * blockDim.x + threadIdx.x;
    if (i < NNODES) g_deg[i] = 0;
    if (i < 2048) { if (w[2 * i + 1]) g_not64 = 1; }
}

// ---------------- 2: convert x, count degrees ----------------
__global__ void prep2_kernel(const void* __restrict__ ei,
                             const void* __restrict__ x) {
    int e = blockIdx.x * blockDim.x + threadIdx.x;
    int is32 = g_not64;
    if (e < NEDGES) {
        int d = ld_edge(ei, is32, NEDGES + e);
        atomicAdd(&g_deg[d], 1);
    }
    if (e < NNODES) {
        g_xi[e] = is32 ? ((const int*)x)[e] : (int)((const long long*)x)[e];
    }
}

// ---------------- 3: exclusive scan of deg -> ptr/cur, and invs ----------------
__global__ __launch_bounds__(1024)
void scaninvs_kernel() {
    __shared__ int part[1024];
    int t = threadIdx.x;
    int lo = t * 49;
    int hi = lo + 49; if (hi > NNODES) hi = NNODES;
    int sum = 0;
    for (int i = lo; i < hi; i++) sum += g_deg[i];
    part[t] = sum;
    __syncthreads();
    for (int off = 1; off < 1024; off <<= 1) {
        int v = (t >= off) ? part[t - off] : 0;
        __syncthreads();
        part[t] += v;
        __syncthreads();
    }
    int base = (t > 0) ? part[t - 1] : 0;
    for (int i = lo; i < hi; i++) {
        g_ptr[i] = base;
        g_cur[i] = base;
        g_invs[i] = rsqrtf((float)g_deg[i] + 1.0f);
        base += g_deg[i];
    }
}

// ---------------- 4: fill dual CSR adjacency, 2 edges/thread ----------------
__global__ void fill_kernel(const void* __restrict__ ei) {
    int t = blockIdx.x * blockDim.x + threadIdx.x;
    int is32 = g_not64;
#pragma unroll
    for (int j = 0; j < 2; j++) {
        int e = t * 2 + j;
        if (e >= NEDGES) return;
        int s = ld_edge(ei, is32, e);
        int d = ld_edge(ei, is32, NEDGES + e);
        float norm = g_invs[s] * g_invs[d];
        int nb = __float_as_int(norm);
        int pos = atomicAdd(&g_cur[d], 1);
        g_adj1[pos] = make_int2(g_xi[s], nb);
        g_adj2[pos] = make_int2(s, nb);
    }
}

// ---------------- emb fp32 -> fp16 ----------------
__global__ void emb2h_kernel(const float* __restrict__ emb) {
    int i = blockIdx.x * blockDim.x + threadIdx.x;   // one per 4 floats
    if (i >= 4096 * FDIM / 4) return;
    float4 v = reinterpret_cast<const float4*>(emb)[i];
    __half2 h0 = __float22half2_rn(make_float2(v.x, v.y));
    __half2 h1 = __float22half2_rn(make_float2(v.z, v.w));
    reinterpret_cast<uint2*>(g_embh)[i] =
        make_uint2(*reinterpret_cast<uint32_t*>(&h0),
                   *reinterpret_cast<uint32_t*>(&h1));
}

// ---------------- weight transpose fp16 ----------------
__global__ void wt_kernel(const float* __restrict__ W1,
                          const float* __restrict__ W2) {
    int t = blockIdx.x * blockDim.x + threadIdx.x;
    if (t < FDIM * HDIM2) {               // W1: [128][256] -> W1T [256][128]
        int n = t / FDIM, k = t % FDIM;
        g_w1t[(size_t)n * FDIM + k] = __float2half(W1[(size_t)k * HDIM2 + n]);
    } else if (t < 2 * FDIM * HDIM2) {    // W2: [256][128] -> W2T [128][256]
        int u = t - FDIM * HDIM2;
        int n = u / HDIM2, k = u % HDIM2;
        g_w2t[(size_t)n * HDIM2 + k] = __float2half(W2[(size_t)k * FDIM + n]);
    }
}

// ---------------- gather: one node per 16-lane half-warp ----------------
__device__ __forceinline__ void fma8(float* a, uint4 u, float nk) {
    const __half2* h = reinterpret_cast<const __half2*>(&u);
#pragma unroll
    for (int q = 0; q < 4; q++) {
        float2 f = __half22float2(h[q]);
        a[2 * q]     += nk * f.x;
        a[2 * q + 1] += nk * f.y;
    }
}

__global__ __launch_bounds__(256)
void gather_kernel(const __half* __restrict__ rows,
                   const int2* __restrict__ adj, int use_xi_self,
                   const float* __restrict__ bias,
                   float* __restrict__ outf,
                   __half* __restrict__ outh) {
    int gh = (blockIdx.x * blockDim.x + threadIdx.x) >> 4;   // half-warp id = node
    int sub = threadIdx.x & 15;
    if (gh >= NNODES) return;

    float a[8];
#pragma unroll
    for (int j = 0; j < 8; j++) a[j] = 0.f;

    float iv = g_invs[gh];
    int p0 = g_ptr[gh];
    int cnt = g_deg[gh];
    const int2* ap = adj + p0;

    // self-loop
    {
        int self = use_xi_self ? g_xi[gh] : gh;
        uint4 u = *reinterpret_cast<const uint4*>(rows + (size_t)self * FDIM + sub * 8);
        fma8(a, u, iv * iv);
    }

    int k = 0;
    for (; k + 8 <= cnt; k += 8) {
        int2 e[8];
#pragma unroll
        for (int j = 0; j < 8; j++) e[j] = ap[k + j];
        uint4 u[8];
#pragma unroll
        for (int j = 0; j < 8; j++)
            u[j] = *reinterpret_cast<const uint4*>(rows + (size_t)e[j].x * FDIM + sub * 8);
#pragma unroll
        for (int j = 0; j < 8; j++)
            fma8(a, u[j], __int_as_float(e[j].y));
    }
    for (; k < cnt; k++) {
        int2 e = ap[k];
        uint4 u = *reinterpret_cast<const uint4*>(rows + (size_t)e.x * FDIM + sub * 8);
        fma8(a, u, __int_as_float(e.y));
    }

    if (outf) {
        float4 b0 = *reinterpret_cast<const float4*>(bias + sub * 8);
        float4 b1 = *reinterpret_cast<const float4*>(bias + sub * 8 + 4);
        float4 o0 = make_float4(a[0] + b0.x, a[1] + b0.y, a[2] + b0.z, a[3] + b0.w);
        float4 o1 = make_float4(a[4] + b1.x, a[5] + b1.y, a[6] + b1.z, a[7] + b1.w);
        float* op = outf + (size_t)gh * FDIM + sub * 8;
        *reinterpret_cast<float4*>(op) = o0;
        *reinterpret_cast<float4*>(op + 4) = o1;
    } else {
        uint32_t w[4];
#pragma unroll
        for (int q = 0; q < 4; q++) {
            __half2 h = __float22half2_rn(make_float2(a[2 * q], a[2 * q + 1]));
            w[q] = *reinterpret_cast<uint32_t*>(&h);
        }
        *reinterpret_cast<uint4*>(outh + (size_t)gh * FDIM + sub * 8) =
            make_uint4(w[0], w[1], w[2], w[3]);
    }
}

// ---------------- fp16 HMMA GEMM ----------------
// BM=128, BN=64, BK=32; 8 warps 4(m) x 2(n); warp tile 32x32 = 2x4 m16n8k16.
#define STR 56   // smem row stride in fp16
__global__ __launch_bounds__(256)
void gemm_f16_kernel(const __half* __restrict__ A,
                     const __half* __restrict__ BT,
                     const float* __restrict__ bias,
                     __half* __restrict__ outh,
                     int M, int Ntot, int K, int do_relu) {
    __shared__ __align__(16) __half sm[10752];   // 21504 B
    const int B_A = 0;               // bytes
    const int B_B = 14336;           // 128*56*2

    int tid = threadIdx.x;
    int lane = tid & 31;
    int wid = tid >> 5;
    int wm = wid & 3, wn = wid >> 2;
    int row0 = blockIdx.y * 128;
    int n0 = blockIdx.x * 64;
    uint32_t smb = smem_u32(sm);
    char* smc = reinterpret_cast<char*>(sm);

    float acc[2][4][4];
#pragma unroll
    for (int mt = 0; mt < 2; mt++)
#pragma unroll
        for (int nt = 0; nt < 4; nt++)
#pragma unroll
            for (int q = 0; q < 4; q++) acc[mt][nt][q] = 0.f;

    int arow = tid >> 1, ahalf = tid & 1;     // A: 2 threads/row, 16 fp16 each
    int brow = tid >> 2, bseg = tid & 3;      // B: 4 threads/row, 8 fp16 each
    int nch = K >> 5;

    for (int c = 0; c < nch; c++) {
        {
            bool v = (row0 + arow) < M;
            size_t off = (size_t)(row0 + arow) * K + c * 32 + ahalf * 16;
            uint4 z = make_uint4(0, 0, 0, 0);
            uint4 h0 = z, h1 = z;
            if (v) {
                h0 = *reinterpret_cast<const uint4*>(A + off);
                h1 = *reinterpret_cast<const uint4*>(A + off + 8);
            }
            int bo = (arow * STR + ahalf * 16) * 2;
            *reinterpret_cast<uint4*>(smc + B_A + bo) = h0;
            *reinterpret_cast<uint4*>(smc + B_A + bo + 16) = h1;
        }
        {
            size_t off = (size_t)(n0 + brow) * K + c * 32 + bseg * 8;
            uint4 h = *reinterpret_cast<const uint4*>(BT + off);
            int bo = (brow * STR + bseg * 8) * 2;
            *reinterpret_cast<uint4*>(smc + B_B + bo) = h;
        }
        __syncthreads();

#pragma unroll
        for (int ks = 0; ks < 2; ks++) {
            uint32_t ah[2][4], bh[4][2];
#pragma unroll
            for (int mt = 0; mt < 2; mt++) {
                uint32_t ad = smb +
                    ((wm * 32 + mt * 16 + (lane & 15)) * STR +
                     ks * 16 + ((lane >> 4) << 3)) * 2;
                LDSM4(ah[mt], ad + B_A);
            }
#pragma unroll
            for (int nt = 0; nt < 4; nt++) {
                uint32_t bd = smb +
                    ((wn * 32 + nt * 8 + (lane & 7)) * STR +
                     ks * 16 + ((lane >> 3) & 1) * 8) * 2;
                LDSM2(bh[nt], bd + B_B);
            }
#pragma unroll
            for (int mt = 0; mt < 2; mt++)
#pragma unroll
                for (int nt = 0; nt < 4; nt++)
                    MMA_F16(acc[mt][nt], ah[mt], bh[nt]);
        }
        __syncthreads();
    }

    int g = lane >> 2, t4 = lane & 3;
#pragma unroll
    for (int mt = 0; mt < 2; mt++) {
        int r0g = row0 + wm * 32 + mt * 16 + g;
#pragma unroll
        for (int nt = 0; nt < 4; nt++) {
            int col = n0 + wn * 32 + nt * 8 + 2 * t4;
            float* a = acc[mt][nt];
            if (bias) {
                float2 bv = *reinterpret_cast<const float2*>(bias + col);
                a[0] += bv.x; a[1] += bv.y; a[2] += bv.x; a[3] += bv.y;
            }
            if (do_relu) {
                a[0] = fmaxf(a[0], 0.f); a[1] = fmaxf(a[1], 0.f);
                a[2] = fmaxf(a[2], 0.f); a[3] = fmaxf(a[3], 0.f);
            }
            if (r0g < M) {
                __half2 h = __float22half2_rn(make_float2(a[0], a[1]));
                reinterpret_cast<uint32_t*>(outh)[((size_t)r0g * Ntot + col) >> 1] =
                    *reinterpret_cast<uint32_t*>(&h);
            }
            if (r0g + 8 < M) {
                __half2 h = __float22half2_rn(make_float2(a[2], a[3]));
                reinterpret_cast<uint32_t*>(outh)[((size_t)(r0g + 8) * Ntot + col) >> 1] =
                    *reinterpret_cast<uint32_t*>(&h);
            }
        }
    }
}

// ---------------- launch ----------------
extern "C" void kernel_launch(void* const* d_in, const int* in_sizes, int n_in,
                              void* d_out, int out_size) {
    const void*  x   = d_in[0];
    const void*  ei  = d_in[1];
    const float* emb = (const float*)d_in[2];   // 4096x128
    const float* W1  = (const float*)d_in[3];   // 128x256
    const float* b1  = (const float*)d_in[4];   // 256
    const float* W2  = (const float*)d_in[5];   // 256x128
    const float* b2  = (const float*)d_in[6];   // 128
    float* out = (float*)d_out;                 // 50000x128

    __half *embh, *ah, *h1h, *th, *w1t, *w2t;
    cudaGetSymbolAddress((void**)&embh, g_embh);
    cudaGetSymbolAddress((void**)&ah,   g_ah);
    cudaGetSymbolAddress((void**)&h1h,  g_h1h);
    cudaGetSymbolAddress((void**)&th,   g_th);
    cudaGetSymbolAddress((void**)&w1t,  g_w1t);
    cudaGetSymbolAddress((void**)&w2t,  g_w2t);
    int2 *adj1, *adj2;
    cudaGetSymbolAddress((void**)&adj1, g_adj1);
    cudaGetSymbolAddress((void**)&adj2, g_adj2);

    // 1) zero deg + dtype detect
    prep1_kernel<<<(NNODES + 255) / 256, 256>>>((const unsigned int*)ei);
    // 2) convert x, degree count
    prep2_kernel<<<(NEDGES + 255) / 256, 256>>>(ei, x);
    // 3) scan degrees -> CSR ptr, invs
    scaninvs_kernel<<<1, 1024>>>();
    // 4) fill dual CSR adjacency   <-- ncu capture slot
    fill_kernel<<<(NEDGES / 2 + 255) / 256, 256>>>(ei);
    // 5) emb -> fp16
    emb2h_kernel<<<(4096 * FDIM / 4 + 255) / 256, 256>>>(emb);
    // 6) weight transpose fp16
    wt_kernel<<<(2 * FDIM * HDIM2 + 255) / 256, 256>>>(W1, W2);
    // 7) gather layer 1 (pre-resolved adj1) -> A fp16
    gather_kernel<<<(NNODES * 16 + 255) / 256, 256>>>(embh, adj1, 1, nullptr,
                                                      nullptr, ah);
    // 8) GEMM1: h1 = relu(A @ W1 + b1)   [M=50000, N=256, K=128]
    {
        dim3 grid(HDIM2 / 64, (NNODES + 127) / 128);
        gemm_f16_kernel<<<grid, 256>>>(ah, w1t, b1, h1h,
                                       NNODES, HDIM2, FDIM, 1);
    }
    // 9) GEMM2: t = h1 @ W2              [M=50000, N=128, K=256]
    {
        dim3 grid(FDIM / 64, (NNODES + 127) / 128);
        gemm_f16_kernel<<<grid, 256>>>(h1h, w2t, nullptr, th,
                                       NNODES, FDIM, HDIM2, 0);
    }
    // 10) gather layer 2 (adj2) -> out fp32 (self-loop + bias fused)
    gather_kernel<<<(NNODES * 16 + 255) / 256, 256>>>(th, adj2, 0, b2,
                                                      out, nullptr);
}

// round 16
// speedup vs baseline: 2.3258x; 1.0040x over previous
#include <cuda_runtime.h>
#include <cuda_fp16.h>
#include <cstdint>

#define NNODES 50000
#define NEDGES 800000
#define FDIM   128
#define HDIM2  256

// ---------------- scratch ----------------
__device__ __align__(16) __half g_embh[4096 * FDIM];             // emb as fp16
__device__ __align__(16) __half g_ah[(size_t)NNODES * FDIM];     // A_hat*E[x] fp16
__device__ __align__(16) __half g_h1h[(size_t)NNODES * HDIM2];   // h1 fp16
__device__ __align__(16) __half g_th[(size_t)NNODES * FDIM];     // h1 @ W2 fp16
__device__ float g_invs[NNODES];
__device__ int   g_deg[NNODES];
__device__ int   g_ptr[NNODES];
__device__ int   g_cur[NNODES];
__device__ __align__(16) int4 g_adj[NEDGES];  // (xi[src], src, norm, 0) by dst
__device__ int   g_xi[NNODES];
__device__ int   g_not64 = 0;   // 0 -> int64 input, 1 -> int32 (idempotent)
// fp16 transposed weights: W1T [256][128], W2T [128][256]
__device__ __align__(16) __half g_w1t[HDIM2 * FDIM];
__device__ __align__(16) __half g_w2t[FDIM * HDIM2];

// ---------------- helpers ----------------
__device__ __forceinline__ uint32_t smem_u32(const void* p) {
    uint32_t a;
    asm("{ .reg .u64 t; cvta.to.shared.u64 t, %1; cvt.u32.u64 %0, t; }"
        : "=r"(a) : "l"(p));
    return a;
}

#define LDSM4(r, a) asm volatile( \
    "ldmatrix.sync.aligned.m8n8.x4.shared.b16 {%0,%1,%2,%3}, [%4];" \
    : "=r"((r)[0]), "=r"((r)[1]), "=r"((r)[2]), "=r"((r)[3]) : "r"(a))
#define LDSM2(r, a) asm volatile( \
    "ldmatrix.sync.aligned.m8n8.x2.shared.b16 {%0,%1}, [%2];" \
    : "=r"((r)[0]), "=r"((r)[1]) : "r"(a))
#define MMA_F16(c, a, b) asm volatile( \
    "mma.sync.aligned.m16n8k16.row.col.f32.f16.f16.f32 " \
    "{%0,%1,%2,%3}, {%4,%5,%6,%7}, {%8,%9}, {%0,%1,%2,%3};" \
    : "+f"((c)[0]), "+f"((c)[1]), "+f"((c)[2]), "+f"((c)[3]) \
    : "r"((a)[0]), "r"((a)[1]), "r"((a)[2]), "r"((a)[3]), \
      "r"((b)[0]), "r"((b)[1]))
#define CP16(dst, src) asm volatile( \
    "cp.async.cg.shared.global [%0], [%1], 16;" :: "r"(dst), "l"(src))
#define CP_COMMIT() asm volatile("cp.async.commit_group;")
#define CP_WAIT0()  asm volatile("cp.async.wait_group 0;")

__device__ __forceinline__ int ld_edge(const void* ei, int is32, int idx) {
    return is32 ? ((const int*)ei)[idx] : (int)((const long long*)ei)[idx];
}

// ---------------- 1: zero deg + dtype detect ----------------
__global__ void prep1_kernel(const unsigned int* __restrict__ w) {
    int i = blockIdx.x * blockDim.x + threadIdx.x;
    if (i < NNODES) g_deg[i] = 0;
    if (i < 2048) { if (w[2 * i + 1]) g_not64 = 1; }
}

// ---------------- 2: convert x, count degrees ----------------
__global__ void prep2_kernel(const void* __restrict__ ei,
                             const void* __restrict__ x) {
    int e = blockIdx.x * blockDim.x + threadIdx.x;
    int is32 = g_not64;
    if (e < NEDGES) {
        int d = ld_edge(ei, is32, NEDGES + e);
        atomicAdd(&g_deg[d], 1);
    }
    if (e < NNODES) {
        g_xi[e] = is32 ? ((const int*)x)[e] : (int)((const long long*)x)[e];
    }
}

// ---------------- 3: exclusive scan of deg -> ptr/cur, and invs ----------------
__global__ __launch_bounds__(1024)
void scaninvs_kernel() {
    __shared__ int part[1024];
    int t = threadIdx.x;
    int lo = t * 49;
    int hi = lo + 49; if (hi > NNODES) hi = NNODES;
    int sum = 0;
    for (int i = lo; i < hi; i++) sum += g_deg[i];
    part[t] = sum;
    __syncthreads();
    for (int off = 1; off < 1024; off <<= 1) {
        int v = (t >= off) ? part[t - off] : 0;
        __syncthreads();
        part[t] += v;
        __syncthreads();
    }
    int base = (t > 0) ? part[t - 1] : 0;
    for (int i = lo; i < hi; i++) {
        g_ptr[i] = base;
        g_cur[i] = base;
        g_invs[i] = rsqrtf((float)g_deg[i] + 1.0f);
        base += g_deg[i];
    }
}

// ---------------- 4: fill packed CSR adjacency, 4 edges/thread ----------------
__global__ void fill_kernel(const void* __restrict__ ei) {
    int t = blockIdx.x * blockDim.x + threadIdx.x;
    int is32 = g_not64;
    int e0 = t * 4;
    int s[4], d[4];
#pragma unroll
    for (int j = 0; j < 4; j++) {
        int e = e0 + j;
        if (e < NEDGES) {
            s[j] = ld_edge(ei, is32, e);
            d[j] = ld_edge(ei, is32, NEDGES + e);
        } else { s[j] = -1; }
    }
#pragma unroll
    for (int j = 0; j < 4; j++) {
        if (s[j] < 0) continue;
        float norm = g_invs[s[j]] * g_invs[d[j]];
        int pos = atomicAdd(&g_cur[d[j]], 1);
        g_adj[pos] = make_int4(g_xi[s[j]], s[j], __float_as_int(norm), 0);
    }
}

// ---------------- emb fp32 -> fp16 ----------------
__global__ void emb2h_kernel(const float* __restrict__ emb) {
    int i = blockIdx.x * blockDim.x + threadIdx.x;   // one per 4 floats
    if (i >= 4096 * FDIM / 4) return;
    float4 v = reinterpret_cast<const float4*>(emb)[i];
    __half2 h0 = __float22half2_rn(make_float2(v.x, v.y));
    __half2 h1 = __float22half2_rn(make_float2(v.z, v.w));
    reinterpret_cast<uint2*>(g_embh)[i] =
        make_uint2(*reinterpret_cast<uint32_t*>(&h0),
                   *reinterpret_cast<uint32_t*>(&h1));
}

// ---------------- weight transpose fp16 ----------------
__global__ void wt_kernel(const float* __restrict__ W1,
                          const float* __restrict__ W2) {
    int t = blockIdx.x * blockDim.x + threadIdx.x;
    if (t < FDIM * HDIM2) {               // W1: [128][256] -> W1T [256][128]
        int n = t / FDIM, k = t % FDIM;
        g_w1t[(size_t)n * FDIM + k] = __float2half(W1[(size_t)k * HDIM2 + n]);
    } else if (t < 2 * FDIM * HDIM2) {    // W2: [256][128] -> W2T [128][256]
        int u = t - FDIM * HDIM2;
        int n = u / HDIM2, k = u % HDIM2;
        g_w2t[(size_t)n * HDIM2 + k] = __float2half(W2[(size_t)k * FDIM + n]);
    }
}

// ---------------- gather: one node per 16-lane half-warp ----------------
__device__ __forceinline__ void fma8(float* a, uint4 u, float nk) {
    const __half2* h = reinterpret_cast<const __half2*>(&u);
#pragma unroll
    for (int q = 0; q < 4; q++) {
        float2 f = __half22float2(h[q]);
        a[2 * q]     += nk * f.x;
        a[2 * q + 1] += nk * f.y;
    }
}

__global__ __launch_bounds__(256)
void gather_kernel(const __half* __restrict__ rows,
                   int use_first, int use_xi_self,
                   const float* __restrict__ bias,
                   float* __restrict__ outf,
                   __half* __restrict__ outh) {
    int gh = (blockIdx.x * blockDim.x + threadIdx.x) >> 4;   // half-warp id = node
    int sub = threadIdx.x & 15;
    if (gh >= NNODES) return;

    float a[8];
#pragma unroll
    for (int j = 0; j < 8; j++) a[j] = 0.f;

    float iv = g_invs[gh];
    int p0 = g_ptr[gh];
    int cnt = g_deg[gh];
    const int4* ap = g_adj + p0;

    // self-loop
    {
        int self = use_xi_self ? g_xi[gh] : gh;
        uint4 u = *reinterpret_cast<const uint4*>(rows + (size_t)self * FDIM + sub * 8);
        fma8(a, u, iv * iv);
    }

    int k = 0;
    for (; k + 8 <= cnt; k += 8) {
        int4 e[8];
#pragma unroll
        for (int j = 0; j < 8; j++) e[j] = ap[k + j];
        uint4 u[8];
#pragma unroll
        for (int j = 0; j < 8; j++) {
            int r = use_first ? e[j].x : e[j].y;
            u[j] = *reinterpret_cast<const uint4*>(rows + (size_t)r * FDIM + sub * 8);
        }
#pragma unroll
        for (int j = 0; j < 8; j++)
            fma8(a, u[j], __int_as_float(e[j].z));
    }
    for (; k < cnt; k++) {
        int4 e = ap[k];
        int r = use_first ? e.x : e.y;
        uint4 u = *reinterpret_cast<const uint4*>(rows + (size_t)r * FDIM + sub * 8);
        fma8(a, u, __int_as_float(e.z));
    }

    if (outf) {
        float4 b0 = *reinterpret_cast<const float4*>(bias + sub * 8);
        float4 b1 = *reinterpret_cast<const float4*>(bias + sub * 8 + 4);
        float4 o0 = make_float4(a[0] + b0.x, a[1] + b0.y, a[2] + b0.z, a[3] + b0.w);
        float4 o1 = make_float4(a[4] + b1.x, a[5] + b1.y, a[6] + b1.z, a[7] + b1.w);
        float* op = outf + (size_t)gh * FDIM + sub * 8;
        *reinterpret_cast<float4*>(op) = o0;
        *reinterpret_cast<float4*>(op + 4) = o1;
    } else {
        uint32_t w[4];
#pragma unroll
        for (int q = 0; q < 4; q++) {
            __half2 h = __float22half2_rn(make_float2(a[2 * q], a[2 * q + 1]));
            w[q] = *reinterpret_cast<uint32_t*>(&h);
        }
        *reinterpret_cast<uint4*>(outh + (size_t)gh * FDIM + sub * 8) =
            make_uint4(w[0], w[1], w[2], w[3]);
    }
}

// ---------------- fp16 HMMA GEMM with cp.async double buffering ----------------
// BM=128, BN=64, BK=32; 8 warps 4(m) x 2(n); warp tile 32x32 = 2x4 m16n8k16.
#define STR 56        // smem row stride in fp16
#define BUFB 21504    // bytes per buffer: (128+64)*56*2
#define OFS_B 14336   // B offset within buffer: 128*56*2
__global__ __launch_bounds__(256)
void gemm_f16_kernel(const __half* __restrict__ A,
                     const __half* __restrict__ BT,
                     const float* __restrict__ bias,
                     __half* __restrict__ outh,
                     int M, int Ntot, int K, int do_relu) {
    __shared__ __align__(16) __half sm[2 * BUFB / 2];

    int tid = threadIdx.x;
    int lane = tid & 31;
    int wid = tid >> 5;
    int wm = wid & 3, wn = wid >> 2;
    int row0 = blockIdx.y * 128;
    int n0 = blockIdx.x * 64;
    uint32_t smb = smem_u32(sm);

    float acc[2][4][4];
#pragma unroll
    for (int mt = 0; mt < 2; mt++)
#pragma unroll
        for (int nt = 0; nt < 4; nt++)
#pragma unroll
            for (int q = 0; q < 4; q++) acc[mt][nt][q] = 0.f;

    int arow = tid >> 1, ahalf = tid & 1;     // A: 2 threads/row, 16 fp16 each
    int brow = tid >> 2, bseg = tid & 3;      // B: 4 threads/row, 8 fp16 each
    int nch = K >> 5;

    int agr = row0 + arow; if (agr > M - 1) agr = M - 1;   // clamp (rows unstored)
    const __half* abase = A + (size_t)agr * K + ahalf * 16;
    const __half* bbase = BT + (size_t)(n0 + brow) * K + bseg * 8;
    uint32_t adst = smb + (arow * STR + ahalf * 16) * 2;
    uint32_t bdst = smb + OFS_B + (brow * STR + bseg * 8) * 2;

    // prologue: chunk 0 -> buffer 0
    CP16(adst, abase);
    CP16(adst + 16, abase + 8);
    CP16(bdst, bbase);
    CP_COMMIT();

    for (int c = 0; c < nch; c++) {
        CP_WAIT0();
        __syncthreads();
        uint32_t buf = (c & 1) ? BUFB : 0;
        if (c + 1 < nch) {
            uint32_t nbuf = ((c + 1) & 1) ? BUFB : 0;
            const __half* an = abase + (c + 1) * 32;
            const __half* bn = bbase + (c + 1) * 32;
            CP16(adst + nbuf, an);
            CP16(adst + nbuf + 16, an + 8);
            CP16(bdst + nbuf, bn);
            CP_COMMIT();
        }
#pragma unroll
        for (int ks = 0; ks < 2; ks++) {
            uint32_t ah[2][4], bh[4][2];
#pragma unroll
            for (int mt = 0; mt < 2; mt++) {
                uint32_t ad = smb + buf +
                    ((wm * 32 + mt * 16 + (lane & 15)) * STR +
                     ks * 16 + ((lane >> 4) << 3)) * 2;
                LDSM4(ah[mt], ad);
            }
#pragma unroll
            for (int nt = 0; nt < 4; nt++) {
                uint32_t bd = smb + buf + OFS_B +
                    ((wn * 32 + nt * 8 + (lane & 7)) * STR +
                     ks * 16 + ((lane >> 3) & 1) * 8) * 2;
                LDSM2(bh[nt], bd);
            }
#pragma unroll
            for (int mt = 0; mt < 2; mt++)
#pragma unroll
                for (int nt = 0; nt < 4; nt++)
                    MMA_F16(acc[mt][nt], ah[mt], bh[nt]);
        }
        __syncthreads();
    }

    int g = lane >> 2, t4 = lane & 3;
#pragma unroll
    for (int mt = 0; mt < 2; mt++) {
        int r0g = row0 + wm * 32 + mt * 16 + g;
#pragma unroll
        for (int nt = 0; nt < 4; nt++) {
            int col = n0 + wn * 32 + nt * 8 + 2 * t4;
            float* a = acc[mt][nt];
            if (bias) {
                float2 bv = *reinterpret_cast<const float2*>(bias + col);
                a[0] += bv.x; a[1] += bv.y; a[2] += bv.x; a[3] += bv.y;
            }
            if (do_relu) {
                a[0] = fmaxf(a[0], 0.f); a[1] = fmaxf(a[1], 0.f);
                a[2] = fmaxf(a[2], 0.f); a[3] = fmaxf(a[3], 0.f);
            }
            if (r0g < M) {
                __half2 h = __float22half2_rn(make_float2(a[0], a[1]));
                reinterpret_cast<uint32_t*>(outh)[((size_t)r0g * Ntot + col) >> 1] =
                    *reinterpret_cast<uint32_t*>(&h);
            }
            if (r0g + 8 < M) {
                __half2 h = __float22half2_rn(make_float2(a[2], a[3]));
                reinterpret_cast<uint32_t*>(outh)[((size_t)(r0g + 8) * Ntot + col) >> 1] =
                    *reinterpret_cast<uint32_t*>(&h);
            }
        }
    }
}

// ---------------- launch ----------------
extern "C" void kernel_launch(void* const* d_in, const int* in_sizes, int n_in,
                              void* d_out, int out_size) {
    const void*  x   = d_in[0];
    const void*  ei  = d_in[1];
    const float* emb = (const float*)d_in[2];   // 4096x128
    const float* W1  = (const float*)d_in[3];   // 128x256
    const float* b1  = (const float*)d_in[4];   // 256
    const float* W2  = (const float*)d_in[5];   // 256x128
    const float* b2  = (const float*)d_in[6];   // 128
    float* out = (float*)d_out;                 // 50000x128

    __half *embh, *ah, *h1h, *th, *w1t, *w2t;
    cudaGetSymbolAddress((void**)&embh, g_embh);
    cudaGetSymbolAddress((void**)&ah,   g_ah);
    cudaGetSymbolAddress((void**)&h1h,  g_h1h);
    cudaGetSymbolAddress((void**)&th,   g_th);
    cudaGetSymbolAddress((void**)&w1t,  g_w1t);
    cudaGetSymbolAddress((void**)&w2t,  g_w2t);

    // 1) zero deg + dtype detect
    prep1_kernel<<<(NNODES + 255) / 256, 256>>>((const unsigned int*)ei);
    // 2) convert x, degree count
    prep2_kernel<<<(NEDGES + 255) / 256, 256>>>(ei, x);
    // 3) scan degrees -> CSR ptr, invs
    scaninvs_kernel<<<1, 1024>>>();
    // 4) fill packed CSR adjacency   <-- ncu capture slot
    fill_kernel<<<(NEDGES / 4 + 255) / 256, 256>>>(ei);
    // 5) emb -> fp16
    emb2h_kernel<<<(4096 * FDIM / 4 + 255) / 256, 256>>>(emb);
    // 6) weight transpose fp16
    wt_kernel<<<(2 * FDIM * HDIM2 + 255) / 256, 256>>>(W1, W2);
    // 7) gather layer 1 (row = adj.x = xi[src]) -> A fp16
    gather_kernel<<<(NNODES * 16 + 255) / 256, 256>>>(embh, 1, 1, nullptr,
                                                      nullptr, ah);
    // 8) GEMM1: h1 = relu(A @ W1 + b1)   [M=50000, N=256, K=128]
    {
        dim3 grid(HDIM2 / 64, (NNODES + 127) / 128);
        gemm_f16_kernel<<<grid, 256>>>(ah, w1t, b1, h1h,
                                       NNODES, HDIM2, FDIM, 1);
    }
    // 9) GEMM2: t = h1 @ W2              [M=50000, N=128, K=256]
    {
        dim3 grid(FDIM / 64, (NNODES + 127) / 128);
        gemm_f16_kernel<<<grid, 256>>>(h1h, w2t, nullptr, th,
                                       NNODES, FDIM, HDIM2, 0);
    }
    // 10) gather layer 2 (row = adj.y = src) -> out fp32 (self-loop + bias fused)
    gather_kernel<<<(NNODES * 16 + 255) / 256, 256>>>(th, 0, 0, b2,
                                                      out, nullptr);
}